// round 1
// baseline (speedup 1.0000x reference)
#include <cuda_runtime.h>

#define EMB  1024
#define NH   16
#define HD   64
#define BSZ  4
#define SEQ  2048
#define BH   (BSZ*NH)

// Scratch (no allocations allowed)
__device__ float g_q[BH*SEQ*HD];
__device__ float g_k[BH*SEQ*HD];
__device__ float g_v[BH*SEQ*HD];
__device__ float g_m[BSZ*SEQ*EMB];

// C = A[M,K] @ W[N,K]^T.  MODE 0: C row-major [M,N].  MODE 1: head-split [B,H,S,D].
template<int MODE>
__global__ void __launch_bounds__(256) sgemm_nt(const float* __restrict__ A,
                                               const float* __restrict__ W,
                                               float* __restrict__ C,
                                               int M, int N, int K)
{
    __shared__ float As[8][128];
    __shared__ float Bs[8][128];
    const int bm = blockIdx.y * 128, bn = blockIdx.x * 128;
    const int tid = threadIdx.x;
    const int lrow = tid >> 1, lcol = (tid & 1) * 4;
    const float* Ap = A + (bm + lrow) * K + lcol;
    const float* Wp = W + (bn + lrow) * K + lcol;
    const int ty = tid >> 4, tx = tid & 15;

    float acc[8][8];
#pragma unroll
    for (int i = 0; i < 8; i++)
#pragma unroll
        for (int j = 0; j < 8; j++) acc[i][j] = 0.f;

    for (int k0 = 0; k0 < K; k0 += 8) {
        float4 a = *(const float4*)(Ap + k0);
        float4 w = *(const float4*)(Wp + k0);
        As[lcol+0][lrow] = a.x; As[lcol+1][lrow] = a.y;
        As[lcol+2][lrow] = a.z; As[lcol+3][lrow] = a.w;
        Bs[lcol+0][lrow] = w.x; Bs[lcol+1][lrow] = w.y;
        Bs[lcol+2][lrow] = w.z; Bs[lcol+3][lrow] = w.w;
        __syncthreads();
#pragma unroll
        for (int k = 0; k < 8; k++) {
            float4 a0 = *(const float4*)&As[k][ty*8];
            float4 a1 = *(const float4*)&As[k][ty*8+4];
            float4 b0 = *(const float4*)&Bs[k][tx*8];
            float4 b1 = *(const float4*)&Bs[k][tx*8+4];
            float ra[8] = {a0.x,a0.y,a0.z,a0.w,a1.x,a1.y,a1.z,a1.w};
            float rb[8] = {b0.x,b0.y,b0.z,b0.w,b1.x,b1.y,b1.z,b1.w};
#pragma unroll
            for (int i = 0; i < 8; i++)
#pragma unroll
                for (int j = 0; j < 8; j++)
                    acc[i][j] += ra[i]*rb[j];
        }
        __syncthreads();
    }

#pragma unroll
    for (int i = 0; i < 8; i++)
#pragma unroll
        for (int j = 0; j < 8; j++) {
            int m = bm + ty*8 + i, n = bn + tx*8 + j;
            if (MODE == 0) {
                C[m*N + n] = acc[i][j];
            } else {
                int bb = m >> 11, ss = m & (SEQ-1);
                int h  = n >> 6,  d  = n & 63;
                C[(((bb*NH + h)*SEQ + ss) << 6) + d] = acc[i][j];
            }
        }
}

// Flash-style causal attention, fp32. Q,K,V: [B,H,S,D]; Out merged [B,S,E].
// grid(32, 64), block 256. Dyn smem: 3 * 64 * 65 floats.
__global__ void __launch_bounds__(256) attn_fwd(const float* __restrict__ Qg,
                                               const float* __restrict__ Kg,
                                               const float* __restrict__ Vg,
                                               float* __restrict__ Out)
{
    extern __shared__ float sm[];
    const int LD = 65;
    float* Qs = sm;                 // 64 x LD
    float* Ks = sm + 64*LD;         // 64 x LD (reused as P)
    float* Vs = sm + 2*64*LD;       // 64 x LD

    const int qt = blockIdx.x, bh = blockIdx.y;
    const int b = bh >> 4, h = bh & 15;
    const float* Qb = Qg + (bh*SEQ + qt*64)*HD;
    const float* Kb = Kg + bh*SEQ*HD;
    const float* Vb = Vg + bh*SEQ*HD;

    const int tid = threadIdx.x;
    const int ty = tid >> 4, tx = tid & 15;
    const int r0 = ty*4, c0 = tx*4;

    // load Q tile (64x64 floats, coalesced float4)
    for (int i = tid; i < 64*16; i += 256) {
        int r = i >> 4, c4 = (i & 15) << 2;
        float4 v = *(const float4*)(Qb + r*HD + c4);
        float* p = Qs + r*LD + c4;
        p[0]=v.x; p[1]=v.y; p[2]=v.z; p[3]=v.w;
    }

    float mi[4], li[4], o[4][4];
#pragma unroll
    for (int i = 0; i < 4; i++) {
        mi[i] = -1e30f; li[i] = 0.f;
#pragma unroll
        for (int j = 0; j < 4; j++) o[i][j] = 0.f;
    }
    __syncthreads();

    for (int kt = 0; kt <= qt; kt++) {
        for (int i = tid; i < 64*16; i += 256) {
            int r = i >> 4, c4 = (i & 15) << 2;
            float4 kv = *(const float4*)(Kb + (kt*64 + r)*HD + c4);
            float* p = Ks + r*LD + c4;
            p[0]=kv.x; p[1]=kv.y; p[2]=kv.z; p[3]=kv.w;
            float4 vv = *(const float4*)(Vb + (kt*64 + r)*HD + c4);
            float* q = Vs + r*LD + c4;
            q[0]=vv.x; q[1]=vv.y; q[2]=vv.z; q[3]=vv.w;
        }
        __syncthreads();

        // S = scale * Q K^T
        float s[4][4];
#pragma unroll
        for (int i = 0; i < 4; i++)
#pragma unroll
            for (int j = 0; j < 4; j++) s[i][j] = 0.f;

        for (int d = 0; d < HD; d++) {
            float qv[4], kv[4];
#pragma unroll
            for (int i = 0; i < 4; i++) qv[i] = Qs[(r0+i)*LD + d];
#pragma unroll
            for (int j = 0; j < 4; j++) kv[j] = Ks[(c0+j)*LD + d];
#pragma unroll
            for (int i = 0; i < 4; i++)
#pragma unroll
                for (int j = 0; j < 4; j++)
                    s[i][j] += qv[i]*kv[j];
        }

        const float scale = 0.125f;  // 1/sqrt(64)
#pragma unroll
        for (int i = 0; i < 4; i++)
#pragma unroll
            for (int j = 0; j < 4; j++) s[i][j] *= scale;

        if (kt == qt) {
#pragma unroll
            for (int i = 0; i < 4; i++)
#pragma unroll
                for (int j = 0; j < 4; j++)
                    if (c0 + j > r0 + i) s[i][j] = -1e30f;
        }

        // online softmax: row max / sum over 16-lane groups (xor 1,2,4,8)
        float mn[4], corr[4];
#pragma unroll
        for (int i = 0; i < 4; i++) {
            float v = fmaxf(fmaxf(s[i][0], s[i][1]), fmaxf(s[i][2], s[i][3]));
#pragma unroll
            for (int msk = 1; msk < 16; msk <<= 1)
                v = fmaxf(v, __shfl_xor_sync(0xffffffffu, v, msk));
            mn[i]   = fmaxf(mi[i], v);
            corr[i] = __expf(mi[i] - mn[i]);
            mi[i]   = mn[i];
        }
#pragma unroll
        for (int i = 0; i < 4; i++) {
            float sum = 0.f;
#pragma unroll
            for (int j = 0; j < 4; j++) {
                s[i][j] = __expf(s[i][j] - mn[i]);
                sum += s[i][j];
            }
#pragma unroll
            for (int msk = 1; msk < 16; msk <<= 1)
                sum += __shfl_xor_sync(0xffffffffu, sum, msk);
            li[i] = li[i]*corr[i] + sum;
#pragma unroll
            for (int j = 0; j < 4; j++) o[i][j] *= corr[i];
        }

        __syncthreads();  // all warps done reading Ks before reuse as P
#pragma unroll
        for (int i = 0; i < 4; i++)
#pragma unroll
            for (int j = 0; j < 4; j++)
                Ks[(r0+i)*LD + (c0+j)] = s[i][j];
        __syncthreads();

        // O += P @ V
        for (int k = 0; k < 64; k++) {
            float pv[4], vv[4];
#pragma unroll
            for (int i = 0; i < 4; i++) pv[i] = Ks[(r0+i)*LD + k];
#pragma unroll
            for (int j = 0; j < 4; j++) vv[j] = Vs[k*LD + (c0+j)];
#pragma unroll
            for (int i = 0; i < 4; i++)
#pragma unroll
                for (int j = 0; j < 4; j++)
                    o[i][j] += pv[i]*vv[j];
        }
        __syncthreads();  // before next K/V tile load
    }

    // write merged heads: Out[b][q][h*64+d]
#pragma unroll
    for (int i = 0; i < 4; i++) {
        float inv = 1.0f / li[i];
#pragma unroll
        for (int j = 0; j < 4; j++) {
            int qr = qt*64 + r0 + i;
            Out[(b*SEQ + qr)*EMB + h*HD + c0 + j] = o[i][j] * inv;
        }
    }
}

extern "C" void kernel_launch(void* const* d_in, const int* in_sizes, int n_in,
                              void* d_out, int out_size)
{
    const float* x  = (const float*)d_in[0];
    const float* Wq = (const float*)d_in[1];
    const float* Wk = (const float*)d_in[2];
    const float* Wv = (const float*)d_in[3];
    const float* Wo = (const float*)d_in[4];
    float* out = (float*)d_out;

    float *q, *k, *v, *m;
    cudaGetSymbolAddress((void**)&q, g_q);
    cudaGetSymbolAddress((void**)&k, g_k);
    cudaGetSymbolAddress((void**)&v, g_v);
    cudaGetSymbolAddress((void**)&m, g_m);

    const int M = BSZ*SEQ, N = EMB, K = EMB;
    dim3 ggrid(N/128, M/128);

    sgemm_nt<1><<<ggrid, 256>>>(x, Wq, q, M, N, K);
    sgemm_nt<1><<<ggrid, 256>>>(x, Wk, k, M, N, K);
    sgemm_nt<1><<<ggrid, 256>>>(x, Wv, v, M, N, K);

    const int smem = 3 * 64 * 65 * (int)sizeof(float);
    cudaFuncSetAttribute(attn_fwd, cudaFuncAttributeMaxDynamicSharedMemorySize, smem);
    attn_fwd<<<dim3(SEQ/64, BH), 256, smem>>>(q, k, v, m);

    sgemm_nt<0><<<ggrid, 256>>>(m, Wo, out, M, N, K);
}

// round 5
// speedup vs baseline: 1.4707x; 1.4707x over previous
#include <cuda_runtime.h>
#include <cstdint>

#define EMB  1024
#define NH   16
#define HD   64
#define BSZ  4
#define SEQ  2048
#define BH   (BSZ*NH)

// Scratch (no allocations allowed)
__device__ float g_q[BH*SEQ*HD];
__device__ float g_k[BH*SEQ*HD];
__device__ float g_v[BH*SEQ*HD];
__device__ float g_m[BSZ*SEQ*EMB];

__device__ __forceinline__ float f2tf32f(float v) {
    uint32_t u;
    asm("cvt.rna.tf32.f32 %0, %1;" : "=r"(u) : "f"(v));
    return __uint_as_float(u);
}

// ---------------------------------------------------------------------------
// tf32 tensor-core GEMM via mma.sync (m16n8k8):  C = A[M,K] @ W[N,K]^T
// Block 256 thr = 8 warps (2 m x 4 n), tile 128x128, K-chunk 32, dbl-buffered.
// SMEM holds fragments in register order:
//   A frag (mt,ks): 32 lanes x 4 regs  -> LDS.128 per lane
//   B frag (nt,ks): 32 lanes x 2 regs  -> LDS.64  per lane
// MODE 0: C row-major [M,N].  MODE 1: head-split [B,H,S,D].
// ---------------------------------------------------------------------------
#define TG_SMEM (2 * 8192 * 4)   // 2 stages x (4096 A + 4096 B) floats

template<int MODE>
__global__ void __launch_bounds__(256) tgemm(const float* __restrict__ A,
                                             const float* __restrict__ W,
                                             float* __restrict__ C,
                                             int M, int N, int K)
{
    extern __shared__ float smf[];
    const int tid = threadIdx.x;
    const int wid = tid >> 5, lane = tid & 31;
    const int wm = wid & 1, wn = wid >> 1;
    const int bm = blockIdx.y * 128, bn = blockIdx.x * 128;

    float acc[4][4][4];
#pragma unroll
    for (int i = 0; i < 4; i++)
#pragma unroll
        for (int j = 0; j < 4; j++)
#pragma unroll
            for (int r = 0; r < 4; r++) acc[i][j][r] = 0.f;

    const int KIT = K / 32;

    // per-thread gmem->frag-smem scatter indices (same for A and B row index)
    int rowv[4], c4v[4], abase[4], bbase[4];
#pragma unroll
    for (int i = 0; i < 4; i++) {
        int idx = tid + i * 256;
        int r = idx >> 3, c = idx & 7;
        rowv[i] = r; c4v[i] = c;
        int mt = r >> 4, r16 = r & 15, ks = c >> 1;
        int rega = (r16 >> 3) + ((c & 1) << 1);
        abase[i] = ((mt * 4 + ks) * 32 + (r16 & 7) * 4) * 4 + rega;
        int nt = r >> 3, nn = r & 7;
        int regb = c & 1;
        bbase[i] = ((nt * 4 + ks) * 32 + nn * 4) * 2 + regb;
    }

    // ---- load chunk 0 ----
    {
        float* da = smf;            // stage 0 A
        float* db = smf + 4096;     // stage 0 B
#pragma unroll
        for (int i = 0; i < 4; i++) {
            const float4 va = *(const float4*)(A + (size_t)(bm + rowv[i]) * K + c4v[i] * 4);
            const float4 vb = *(const float4*)(W + (size_t)(bn + rowv[i]) * K + c4v[i] * 4);
            da[abase[i] + 0]  = f2tf32f(va.x);
            da[abase[i] + 4]  = f2tf32f(va.y);
            da[abase[i] + 8]  = f2tf32f(va.z);
            da[abase[i] + 12] = f2tf32f(va.w);
            db[bbase[i] + 0]  = f2tf32f(vb.x);
            db[bbase[i] + 2]  = f2tf32f(vb.y);
            db[bbase[i] + 4]  = f2tf32f(vb.z);
            db[bbase[i] + 6]  = f2tf32f(vb.w);
        }
    }
    __syncthreads();

    for (int it = 0; it < KIT; it++) {
        float4 pa[4], pb[4];
        const bool pref = (it + 1 < KIT);
        if (pref) {
            const int ko = (it + 1) * 32;
#pragma unroll
            for (int i = 0; i < 4; i++) {
                pa[i] = *(const float4*)(A + (size_t)(bm + rowv[i]) * K + ko + c4v[i] * 4);
                pb[i] = *(const float4*)(W + (size_t)(bn + rowv[i]) * K + ko + c4v[i] * 4);
            }
        }

        const float* sa = smf + (it & 1) * 8192;
        const float* sb = sa + 4096;

#pragma unroll
        for (int ks = 0; ks < 4; ks++) {
            uint32_t af[4][4], bf[4][2];
#pragma unroll
            for (int i = 0; i < 4; i++) {
                const int mt = wm * 4 + i;
                const float4 v = *(const float4*)(sa + ((mt * 4 + ks) * 32 + lane) * 4);
                af[i][0] = __float_as_uint(v.x); af[i][1] = __float_as_uint(v.y);
                af[i][2] = __float_as_uint(v.z); af[i][3] = __float_as_uint(v.w);
            }
#pragma unroll
            for (int j = 0; j < 4; j++) {
                const int nt = wn * 4 + j;
                const float2 v = *(const float2*)(sb + ((nt * 4 + ks) * 32 + lane) * 2);
                bf[j][0] = __float_as_uint(v.x); bf[j][1] = __float_as_uint(v.y);
            }
#pragma unroll
            for (int i = 0; i < 4; i++)
#pragma unroll
                for (int j = 0; j < 4; j++) {
                    asm volatile(
                        "mma.sync.aligned.m16n8k8.row.col.f32.tf32.tf32.f32 "
                        "{%0,%1,%2,%3}, {%4,%5,%6,%7}, {%8,%9}, {%0,%1,%2,%3};"
                        : "+f"(acc[i][j][0]), "+f"(acc[i][j][1]),
                          "+f"(acc[i][j][2]), "+f"(acc[i][j][3])
                        : "r"(af[i][0]), "r"(af[i][1]), "r"(af[i][2]), "r"(af[i][3]),
                          "r"(bf[j][0]), "r"(bf[j][1]));
                }
        }

        if (pref) {
            float* da = smf + ((it + 1) & 1) * 8192;
            float* db = da + 4096;
#pragma unroll
            for (int i = 0; i < 4; i++) {
                da[abase[i] + 0]  = f2tf32f(pa[i].x);
                da[abase[i] + 4]  = f2tf32f(pa[i].y);
                da[abase[i] + 8]  = f2tf32f(pa[i].z);
                da[abase[i] + 12] = f2tf32f(pa[i].w);
                db[bbase[i] + 0]  = f2tf32f(pb[i].x);
                db[bbase[i] + 2]  = f2tf32f(pb[i].y);
                db[bbase[i] + 4]  = f2tf32f(pb[i].z);
                db[bbase[i] + 6]  = f2tf32f(pb[i].w);
            }
        }
        __syncthreads();
    }

    // epilogue
#pragma unroll
    for (int i = 0; i < 4; i++) {
#pragma unroll
        for (int j = 0; j < 4; j++) {
            const int m0 = bm + wm * 64 + i * 16 + (lane >> 2);
            const int n0 = bn + wn * 32 + j * 8 + (lane & 3) * 2;
            float2 lo = { acc[i][j][0], acc[i][j][1] };
            float2 hi = { acc[i][j][2], acc[i][j][3] };
            if (MODE == 0) {
                *(float2*)(C + (size_t)m0 * N + n0) = lo;
                *(float2*)(C + (size_t)(m0 + 8) * N + n0) = hi;
            } else {
                const int h = n0 >> 6, d = n0 & 63;
                const int b0 = m0 >> 11, s0 = m0 & (SEQ - 1);
                *(float2*)(C + ((size_t)((b0*NH + h)*SEQ + s0) << 6) + d) = lo;
                const int m1 = m0 + 8;
                const int b1 = m1 >> 11, s1 = m1 & (SEQ - 1);
                *(float2*)(C + ((size_t)((b1*NH + h)*SEQ + s1) << 6) + d) = hi;
            }
        }
    }
}

// ---------------------------------------------------------------------------
// Flash-style causal attention, fp32 (unchanged; tensorize next round)
// ---------------------------------------------------------------------------
__global__ void __launch_bounds__(256) attn_fwd(const float* __restrict__ Qg,
                                               const float* __restrict__ Kg,
                                               const float* __restrict__ Vg,
                                               float* __restrict__ Out)
{
    extern __shared__ float sm[];
    const int LD = 65;
    float* Qs = sm;
    float* Ks = sm + 64*LD;
    float* Vs = sm + 2*64*LD;

    const int qt = blockIdx.x, bh = blockIdx.y;
    const int b = bh >> 4, h = bh & 15;
    const float* Qb = Qg + (bh*SEQ + qt*64)*HD;
    const float* Kb = Kg + bh*SEQ*HD;
    const float* Vb = Vg + bh*SEQ*HD;

    const int tid = threadIdx.x;
    const int ty = tid >> 4, tx = tid & 15;
    const int r0 = ty*4, c0 = tx*4;

    for (int i = tid; i < 64*16; i += 256) {
        int r = i >> 4, c4 = (i & 15) << 2;
        float4 v = *(const float4*)(Qb + r*HD + c4);
        float* p = Qs + r*LD + c4;
        p[0]=v.x; p[1]=v.y; p[2]=v.z; p[3]=v.w;
    }

    float mi[4], li[4], o[4][4];
#pragma unroll
    for (int i = 0; i < 4; i++) {
        mi[i] = -1e30f; li[i] = 0.f;
#pragma unroll
        for (int j = 0; j < 4; j++) o[i][j] = 0.f;
    }
    __syncthreads();

    for (int kt = 0; kt <= qt; kt++) {
        for (int i = tid; i < 64*16; i += 256) {
            int r = i >> 4, c4 = (i & 15) << 2;
            float4 kv = *(const float4*)(Kb + (kt*64 + r)*HD + c4);
            float* p = Ks + r*LD + c4;
            p[0]=kv.x; p[1]=kv.y; p[2]=kv.z; p[3]=kv.w;
            float4 vv = *(const float4*)(Vb + (kt*64 + r)*HD + c4);
            float* q = Vs + r*LD + c4;
            q[0]=vv.x; q[1]=vv.y; q[2]=vv.z; q[3]=vv.w;
        }
        __syncthreads();

        float s[4][4];
#pragma unroll
        for (int i = 0; i < 4; i++)
#pragma unroll
            for (int j = 0; j < 4; j++) s[i][j] = 0.f;

        for (int d = 0; d < HD; d++) {
            float qv[4], kv[4];
#pragma unroll
            for (int i = 0; i < 4; i++) qv[i] = Qs[(r0+i)*LD + d];
#pragma unroll
            for (int j = 0; j < 4; j++) kv[j] = Ks[(c0+j)*LD + d];
#pragma unroll
            for (int i = 0; i < 4; i++)
#pragma unroll
                for (int j = 0; j < 4; j++)
                    s[i][j] += qv[i]*kv[j];
        }

        const float scale = 0.125f;
#pragma unroll
        for (int i = 0; i < 4; i++)
#pragma unroll
            for (int j = 0; j < 4; j++) s[i][j] *= scale;

        if (kt == qt) {
#pragma unroll
            for (int i = 0; i < 4; i++)
#pragma unroll
                for (int j = 0; j < 4; j++)
                    if (c0 + j > r0 + i) s[i][j] = -1e30f;
        }

        float mn[4], corr[4];
#pragma unroll
        for (int i = 0; i < 4; i++) {
            float v = fmaxf(fmaxf(s[i][0], s[i][1]), fmaxf(s[i][2], s[i][3]));
#pragma unroll
            for (int msk = 1; msk < 16; msk <<= 1)
                v = fmaxf(v, __shfl_xor_sync(0xffffffffu, v, msk));
            mn[i]   = fmaxf(mi[i], v);
            corr[i] = __expf(mi[i] - mn[i]);
            mi[i]   = mn[i];
        }
#pragma unroll
        for (int i = 0; i < 4; i++) {
            float sum = 0.f;
#pragma unroll
            for (int j = 0; j < 4; j++) {
                s[i][j] = __expf(s[i][j] - mn[i]);
                sum += s[i][j];
            }
#pragma unroll
            for (int msk = 1; msk < 16; msk <<= 1)
                sum += __shfl_xor_sync(0xffffffffu, sum, msk);
            li[i] = li[i]*corr[i] + sum;
#pragma unroll
            for (int j = 0; j < 4; j++) o[i][j] *= corr[i];
        }

        __syncthreads();
#pragma unroll
        for (int i = 0; i < 4; i++)
#pragma unroll
            for (int j = 0; j < 4; j++)
                Ks[(r0+i)*LD + (c0+j)] = s[i][j];
        __syncthreads();

        for (int k = 0; k < 64; k++) {
            float pv[4], vv[4];
#pragma unroll
            for (int i = 0; i < 4; i++) pv[i] = Ks[(r0+i)*LD + k];
#pragma unroll
            for (int j = 0; j < 4; j++) vv[j] = Vs[k*LD + (c0+j)];
#pragma unroll
            for (int i = 0; i < 4; i++)
#pragma unroll
                for (int j = 0; j < 4; j++)
                    o[i][j] += pv[i]*vv[j];
        }
        __syncthreads();
    }

#pragma unroll
    for (int i = 0; i < 4; i++) {
        float inv = 1.0f / li[i];
#pragma unroll
        for (int j = 0; j < 4; j++) {
            int qr = qt*64 + r0 + i;
            Out[(b*SEQ + qr)*EMB + h*HD + c0 + j] = o[i][j] * inv;
        }
    }
}

extern "C" void kernel_launch(void* const* d_in, const int* in_sizes, int n_in,
                              void* d_out, int out_size)
{
    const float* x  = (const float*)d_in[0];
    const float* Wq = (const float*)d_in[1];
    const float* Wk = (const float*)d_in[2];
    const float* Wv = (const float*)d_in[3];
    const float* Wo = (const float*)d_in[4];
    float* out = (float*)d_out;

    float *q, *k, *v, *m;
    cudaGetSymbolAddress((void**)&q, g_q);
    cudaGetSymbolAddress((void**)&k, g_k);
    cudaGetSymbolAddress((void**)&v, g_v);
    cudaGetSymbolAddress((void**)&m, g_m);

    const int M = BSZ*SEQ, N = EMB, K = EMB;
    dim3 ggrid(N/128, M/128);

    cudaFuncSetAttribute(tgemm<0>, cudaFuncAttributeMaxDynamicSharedMemorySize, TG_SMEM);
    cudaFuncSetAttribute(tgemm<1>, cudaFuncAttributeMaxDynamicSharedMemorySize, TG_SMEM);

    tgemm<1><<<ggrid, 256, TG_SMEM>>>(x, Wq, q, M, N, K);
    tgemm<1><<<ggrid, 256, TG_SMEM>>>(x, Wk, k, M, N, K);
    tgemm<1><<<ggrid, 256, TG_SMEM>>>(x, Wv, v, M, N, K);

    const int smem = 3 * 64 * 65 * (int)sizeof(float);
    cudaFuncSetAttribute(attn_fwd, cudaFuncAttributeMaxDynamicSharedMemorySize, smem);
    attn_fwd<<<dim3(SEQ/64, BH), 256, smem>>>(q, k, v, m);

    tgemm<0><<<ggrid, 256, TG_SMEM>>>(m, Wo, out, M, N, K);
}

// round 6
// speedup vs baseline: 2.1362x; 1.4525x over previous
#include <cuda_runtime.h>
#include <cstdint>

#define EMB  1024
#define NH   16
#define HD   64
#define BSZ  4
#define SEQ  2048
#define BH   (BSZ*NH)

__device__ float g_q[BH*SEQ*HD];
__device__ float g_k[BH*SEQ*HD];
__device__ float g_v[BH*SEQ*HD];
__device__ float g_m[BSZ*SEQ*EMB];

__device__ __forceinline__ uint32_t tfu(float v) {
    uint32_t u;
    asm("cvt.rna.tf32.f32 %0, %1;" : "=r"(u) : "f"(v));
    return u;
}
__device__ __forceinline__ float f2tf32f(float v) { return __uint_as_float(tfu(v)); }

__device__ __forceinline__ void mma_tf32(float* c, const uint32_t* a, float2 b) {
    asm volatile(
        "mma.sync.aligned.m16n8k8.row.col.f32.tf32.tf32.f32 "
        "{%0,%1,%2,%3}, {%4,%5,%6,%7}, {%8,%9}, {%0,%1,%2,%3};"
        : "+f"(c[0]), "+f"(c[1]), "+f"(c[2]), "+f"(c[3])
        : "r"(a[0]), "r"(a[1]), "r"(a[2]), "r"(a[3]),
          "r"(__float_as_uint(b.x)), "r"(__float_as_uint(b.y)));
}

// ---------------------------------------------------------------------------
// tf32 tensor-core GEMM (unchanged from round 4)
// ---------------------------------------------------------------------------
#define TG_SMEM (2 * 8192 * 4)

template<int MODE>
__global__ void __launch_bounds__(256) tgemm(const float* __restrict__ A,
                                             const float* __restrict__ W,
                                             float* __restrict__ C,
                                             int M, int N, int K)
{
    extern __shared__ float smf[];
    const int tid = threadIdx.x;
    const int wid = tid >> 5, lane = tid & 31;
    const int wm = wid & 1, wn = wid >> 1;
    const int bm = blockIdx.y * 128, bn = blockIdx.x * 128;

    float acc[4][4][4];
#pragma unroll
    for (int i = 0; i < 4; i++)
#pragma unroll
        for (int j = 0; j < 4; j++)
#pragma unroll
            for (int r = 0; r < 4; r++) acc[i][j][r] = 0.f;

    const int KIT = K / 32;

    int rowv[4], c4v[4], abase[4], bbase[4];
#pragma unroll
    for (int i = 0; i < 4; i++) {
        int idx = tid + i * 256;
        int r = idx >> 3, c = idx & 7;
        rowv[i] = r; c4v[i] = c;
        int mt = r >> 4, r16 = r & 15, ks = c >> 1;
        int rega = (r16 >> 3) + ((c & 1) << 1);
        abase[i] = ((mt * 4 + ks) * 32 + (r16 & 7) * 4) * 4 + rega;
        int nt = r >> 3, nn = r & 7;
        int regb = c & 1;
        bbase[i] = ((nt * 4 + ks) * 32 + nn * 4) * 2 + regb;
    }

    {
        float* da = smf;
        float* db = smf + 4096;
#pragma unroll
        for (int i = 0; i < 4; i++) {
            const float4 va = *(const float4*)(A + (size_t)(bm + rowv[i]) * K + c4v[i] * 4);
            const float4 vb = *(const float4*)(W + (size_t)(bn + rowv[i]) * K + c4v[i] * 4);
            da[abase[i] + 0]  = f2tf32f(va.x);
            da[abase[i] + 4]  = f2tf32f(va.y);
            da[abase[i] + 8]  = f2tf32f(va.z);
            da[abase[i] + 12] = f2tf32f(va.w);
            db[bbase[i] + 0]  = f2tf32f(vb.x);
            db[bbase[i] + 2]  = f2tf32f(vb.y);
            db[bbase[i] + 4]  = f2tf32f(vb.z);
            db[bbase[i] + 6]  = f2tf32f(vb.w);
        }
    }
    __syncthreads();

    for (int it = 0; it < KIT; it++) {
        float4 pa[4], pb[4];
        const bool pref = (it + 1 < KIT);
        if (pref) {
            const int ko = (it + 1) * 32;
#pragma unroll
            for (int i = 0; i < 4; i++) {
                pa[i] = *(const float4*)(A + (size_t)(bm + rowv[i]) * K + ko + c4v[i] * 4);
                pb[i] = *(const float4*)(W + (size_t)(bn + rowv[i]) * K + ko + c4v[i] * 4);
            }
        }

        const float* sa = smf + (it & 1) * 8192;
        const float* sb = sa + 4096;

#pragma unroll
        for (int ks = 0; ks < 4; ks++) {
            uint32_t af[4][4], bf[4][2];
#pragma unroll
            for (int i = 0; i < 4; i++) {
                const int mt = wm * 4 + i;
                const float4 v = *(const float4*)(sa + ((mt * 4 + ks) * 32 + lane) * 4);
                af[i][0] = __float_as_uint(v.x); af[i][1] = __float_as_uint(v.y);
                af[i][2] = __float_as_uint(v.z); af[i][3] = __float_as_uint(v.w);
            }
#pragma unroll
            for (int j = 0; j < 4; j++) {
                const int nt = wn * 4 + j;
                const float2 v = *(const float2*)(sb + ((nt * 4 + ks) * 32 + lane) * 2);
                bf[j][0] = __float_as_uint(v.x); bf[j][1] = __float_as_uint(v.y);
            }
#pragma unroll
            for (int i = 0; i < 4; i++)
#pragma unroll
                for (int j = 0; j < 4; j++) {
                    asm volatile(
                        "mma.sync.aligned.m16n8k8.row.col.f32.tf32.tf32.f32 "
                        "{%0,%1,%2,%3}, {%4,%5,%6,%7}, {%8,%9}, {%0,%1,%2,%3};"
                        : "+f"(acc[i][j][0]), "+f"(acc[i][j][1]),
                          "+f"(acc[i][j][2]), "+f"(acc[i][j][3])
                        : "r"(af[i][0]), "r"(af[i][1]), "r"(af[i][2]), "r"(af[i][3]),
                          "r"(bf[j][0]), "r"(bf[j][1]));
                }
        }

        if (pref) {
            float* da = smf + ((it + 1) & 1) * 8192;
            float* db = da + 4096;
#pragma unroll
            for (int i = 0; i < 4; i++) {
                da[abase[i] + 0]  = f2tf32f(pa[i].x);
                da[abase[i] + 4]  = f2tf32f(pa[i].y);
                da[abase[i] + 8]  = f2tf32f(pa[i].z);
                da[abase[i] + 12] = f2tf32f(pa[i].w);
                db[bbase[i] + 0]  = f2tf32f(pb[i].x);
                db[bbase[i] + 2]  = f2tf32f(pb[i].y);
                db[bbase[i] + 4]  = f2tf32f(pb[i].z);
                db[bbase[i] + 6]  = f2tf32f(pb[i].w);
            }
        }
        __syncthreads();
    }

#pragma unroll
    for (int i = 0; i < 4; i++) {
#pragma unroll
        for (int j = 0; j < 4; j++) {
            const int m0 = bm + wm * 64 + i * 16 + (lane >> 2);
            const int n0 = bn + wn * 32 + j * 8 + (lane & 3) * 2;
            float2 lo = { acc[i][j][0], acc[i][j][1] };
            float2 hi = { acc[i][j][2], acc[i][j][3] };
            if (MODE == 0) {
                *(float2*)(C + (size_t)m0 * N + n0) = lo;
                *(float2*)(C + (size_t)(m0 + 8) * N + n0) = hi;
            } else {
                const int h = n0 >> 6, d = n0 & 63;
                const int b0 = m0 >> 11, s0 = m0 & (SEQ - 1);
                *(float2*)(C + ((size_t)((b0*NH + h)*SEQ + s0) << 6) + d) = lo;
                const int m1 = m0 + 8;
                const int b1 = m1 >> 11, s1 = m1 & (SEQ - 1);
                *(float2*)(C + ((size_t)((b1*NH + h)*SEQ + s1) << 6) + d) = hi;
            }
        }
    }
}

// ---------------------------------------------------------------------------
// Tensor-core flash attention (tf32 mma.sync), causal.
// Block: 128 q-rows x 1 head, 8 warps (16 rows each). BK=64 keys per tile.
// grid(16, 64), 256 threads.
// SMEM: Qs[128][68] (reused as per-warp P after Q->regs), Kf[4096], Vf[4096].
// ---------------------------------------------------------------------------
#define QLD 68
#define ATT_SMEM ((128*QLD + 4096 + 4096) * 4)

__global__ void __launch_bounds__(256) attn_tc(const float* __restrict__ Qg,
                                               const float* __restrict__ Kg,
                                               const float* __restrict__ Vg,
                                               float* __restrict__ Out)
{
    extern __shared__ float sm[];
    float* Qs = sm;                 // 128 x 68 (reused as P)
    float* Kf = sm + 128*QLD;       // 4096: B-frags (n=key, k=d)
    float* Vf = Kf + 4096;          // 4096: B-frags (n=d, k=key)

    const int qt = (SEQ/128 - 1) - blockIdx.x;   // big tiles first
    const int bh = blockIdx.y;
    const int b = bh >> 4, h = bh & 15;
    const int tid = threadIdx.x, w = tid >> 5, lane = tid & 31;
    const int g = lane >> 2, t = lane & 3;

    const float* Qb = Qg + (size_t)(bh*SEQ + qt*128)*HD;
    const float* Kb = Kg + (size_t)bh*SEQ*HD;
    const float* Vb = Vg + (size_t)bh*SEQ*HD;

    // stage Q coalesced
    for (int i = tid; i < 128*16; i += 256) {
        int r = i >> 4, c4 = (i & 15) << 2;
        float4 v = *(const float4*)(Qb + r*HD + c4);
        float* p = Qs + r*QLD + c4;
        p[0]=v.x; p[1]=v.y; p[2]=v.z; p[3]=v.w;
    }
    __syncthreads();

    // Q A-frags, pre-scaled by 1/sqrt(64)
    uint32_t qf[8][4];
    {
        const float sc = 0.125f;
        const int r0 = w*16 + g;
#pragma unroll
        for (int ks = 0; ks < 8; ks++) {
            int col = ks*8 + t;
            qf[ks][0] = tfu(Qs[r0*QLD + col] * sc);
            qf[ks][1] = tfu(Qs[(r0+8)*QLD + col] * sc);
            qf[ks][2] = tfu(Qs[r0*QLD + col + 4] * sc);
            qf[ks][3] = tfu(Qs[(r0+8)*QLD + col + 4] * sc);
        }
    }
    __syncthreads();      // Qs now free -> per-warp P buffers

    float* Pw = Qs + w*1024;   // 16x64 A-frag-ordered P

    float mrow[2] = { -1e30f, -1e30f };
    float lrow[2] = { 0.f, 0.f };
    float oacc[8][4];
#pragma unroll
    for (int i = 0; i < 8; i++)
#pragma unroll
        for (int r = 0; r < 4; r++) oacc[i][r] = 0.f;

    const int nkt = 2*qt + 2;
    for (int kt = 0; kt < nkt; kt++) {
        // ---- load K,V tile (64x64) into frag-order smem, tf32-rounded ----
        const float* Kt = Kb + (size_t)kt*64*HD;
        const float* Vt = Vb + (size_t)kt*64*HD;
#pragma unroll
        for (int i = 0; i < 4; i++) {
            int f4 = tid + i*256;
            int key = f4 >> 4;
            int d0 = (f4 & 15) * 4;
            float4 kv = *(const float4*)(Kt + key*HD + d0);
            float4 vv = *(const float4*)(Vt + key*HD + d0);
            float kvals[4] = { kv.x, kv.y, kv.z, kv.w };
            float vvals[4] = { vv.x, vv.y, vv.z, vv.w };
            const int knt = key >> 3, klb = (key & 7) * 4;
            const int vks = key >> 3, vrg = (key >> 2) & 1, vkl = key & 3;
#pragma unroll
            for (int e = 0; e < 4; e++) {
                int d = d0 + e;
                Kf[((knt*8 + (d >> 3))*32 + klb + (d & 3))*2 + ((d >> 2) & 1)] = f2tf32f(kvals[e]);
                Vf[(((d >> 3)*8 + vks)*32 + (d & 7)*4 + vkl)*2 + vrg] = f2tf32f(vvals[e]);
            }
        }
        __syncthreads();

        // ---- S = (Q*scale) @ K^T ----
        float sacc[8][4];
#pragma unroll
        for (int nt = 0; nt < 8; nt++)
#pragma unroll
            for (int r = 0; r < 4; r++) sacc[nt][r] = 0.f;

#pragma unroll
        for (int ks = 0; ks < 8; ks++)
#pragma unroll
            for (int nt = 0; nt < 8; nt++) {
                float2 bfr = *(const float2*)(Kf + ((nt*8 + ks)*32 + lane)*2);
                mma_tf32(sacc[nt], qf[ks], bfr);
            }

        // ---- causal mask (only diagonal-straddling tiles) ----
        if (kt >= 2*qt) {
            const int row0 = qt*128 + w*16 + g;
            const int colb = kt*64 + 2*t;
#pragma unroll
            for (int nt = 0; nt < 8; nt++) {
                int c = colb + nt*8;
                if (c     > row0)     sacc[nt][0] = -1e30f;
                if (c + 1 > row0)     sacc[nt][1] = -1e30f;
                if (c     > row0 + 8) sacc[nt][2] = -1e30f;
                if (c + 1 > row0 + 8) sacc[nt][3] = -1e30f;
            }
        }

        // ---- online softmax (2 row-halves per lane) ----
#pragma unroll
        for (int hh = 0; hh < 2; hh++) {
            const int i0 = hh*2;
            float mx = -1e30f;
#pragma unroll
            for (int nt = 0; nt < 8; nt++)
                mx = fmaxf(mx, fmaxf(sacc[nt][i0], sacc[nt][i0+1]));
            mx = fmaxf(mx, __shfl_xor_sync(0xffffffffu, mx, 1));
            mx = fmaxf(mx, __shfl_xor_sync(0xffffffffu, mx, 2));
            float mnew = fmaxf(mrow[hh], mx);
            float corr = __expf(mrow[hh] - mnew);
            mrow[hh] = mnew;
            float sum = 0.f;
#pragma unroll
            for (int nt = 0; nt < 8; nt++) {
                sacc[nt][i0]   = __expf(sacc[nt][i0]   - mnew);
                sacc[nt][i0+1] = __expf(sacc[nt][i0+1] - mnew);
                sum += sacc[nt][i0] + sacc[nt][i0+1];
            }
            sum += __shfl_xor_sync(0xffffffffu, sum, 1);
            sum += __shfl_xor_sync(0xffffffffu, sum, 2);
            lrow[hh] = lrow[hh]*corr + sum;
#pragma unroll
            for (int dt = 0; dt < 8; dt++) {
                oacc[dt][i0]   *= corr;
                oacc[dt][i0+1] *= corr;
            }
        }

        // ---- P -> smem in A-frag order ----
#pragma unroll
        for (int nt = 0; nt < 8; nt++) {
            int k0 = 2*t, k1 = 2*t + 1;
            int a0 = (nt*32 + g*4 + (k0 & 3))*4 + 2*((k0 >> 2) & 1);
            int a1 = (nt*32 + g*4 + (k1 & 3))*4 + 2*((k1 >> 2) & 1);
            Pw[a0]     = f2tf32f(sacc[nt][0]);
            Pw[a1]     = f2tf32f(sacc[nt][1]);
            Pw[a0 + 1] = f2tf32f(sacc[nt][2]);
            Pw[a1 + 1] = f2tf32f(sacc[nt][3]);
        }
        __syncwarp();

        // ---- O += P @ V ----
#pragma unroll
        for (int ks = 0; ks < 8; ks++) {
            float4 p4 = *(const float4*)(Pw + (ks*32 + g*4 + t)*4);
            uint32_t pf[4] = { __float_as_uint(p4.x), __float_as_uint(p4.y),
                               __float_as_uint(p4.z), __float_as_uint(p4.w) };
#pragma unroll
            for (int dt = 0; dt < 8; dt++) {
                float2 bfr = *(const float2*)(Vf + ((dt*8 + ks)*32 + lane)*2);
                mma_tf32(oacc[dt], pf, bfr);
            }
        }
        __syncthreads();   // protect Kf/Vf for next tile
    }

    // ---- epilogue: normalize + write merged [B,S,E] ----
    const float inv0 = 1.0f / lrow[0];
    const float inv1 = 1.0f / lrow[1];
    const int row0 = qt*128 + w*16 + g;
#pragma unroll
    for (int dt = 0; dt < 8; dt++) {
        const int col = h*64 + dt*8 + 2*t;
        float2 lo = { oacc[dt][0]*inv0, oacc[dt][1]*inv0 };
        float2 hi = { oacc[dt][2]*inv1, oacc[dt][3]*inv1 };
        *(float2*)(Out + (size_t)(b*SEQ + row0)*EMB + col) = lo;
        *(float2*)(Out + (size_t)(b*SEQ + row0 + 8)*EMB + col) = hi;
    }
}

extern "C" void kernel_launch(void* const* d_in, const int* in_sizes, int n_in,
                              void* d_out, int out_size)
{
    const float* x  = (const float*)d_in[0];
    const float* Wq = (const float*)d_in[1];
    const float* Wk = (const float*)d_in[2];
    const float* Wv = (const float*)d_in[3];
    const float* Wo = (const float*)d_in[4];
    float* out = (float*)d_out;

    float *q, *k, *v, *m;
    cudaGetSymbolAddress((void**)&q, g_q);
    cudaGetSymbolAddress((void**)&k, g_k);
    cudaGetSymbolAddress((void**)&v, g_v);
    cudaGetSymbolAddress((void**)&m, g_m);

    const int M = BSZ*SEQ, N = EMB, K = EMB;
    dim3 ggrid(N/128, M/128);

    cudaFuncSetAttribute(tgemm<0>, cudaFuncAttributeMaxDynamicSharedMemorySize, TG_SMEM);
    cudaFuncSetAttribute(tgemm<1>, cudaFuncAttributeMaxDynamicSharedMemorySize, TG_SMEM);
    cudaFuncSetAttribute(attn_tc, cudaFuncAttributeMaxDynamicSharedMemorySize, ATT_SMEM);

    tgemm<1><<<ggrid, 256, TG_SMEM>>>(x, Wq, q, M, N, K);
    tgemm<1><<<ggrid, 256, TG_SMEM>>>(x, Wk, k, M, N, K);
    tgemm<1><<<ggrid, 256, TG_SMEM>>>(x, Wv, v, M, N, K);

    attn_tc<<<dim3(SEQ/128, BH), 256, ATT_SMEM>>>(q, k, v, m);

    tgemm<0><<<ggrid, 256, TG_SMEM>>>(m, Wo, out, M, N, K);
}

// round 7
// speedup vs baseline: 2.1787x; 1.0199x over previous
#include <cuda_runtime.h>
#include <cstdint>

#define EMB  1024
#define NH   16
#define HD   64
#define BSZ  4
#define SEQ  2048
#define BH   (BSZ*NH)

__device__ float g_q[BH*SEQ*HD];
__device__ float g_k[BH*SEQ*HD];
__device__ float g_v[BH*SEQ*HD];
__device__ float g_m[BSZ*SEQ*EMB];

__device__ __forceinline__ uint32_t tfu(float v) {
    uint32_t u;
    asm("cvt.rna.tf32.f32 %0, %1;" : "=r"(u) : "f"(v));
    return u;
}
__device__ __forceinline__ float f2tf32f(float v) { return __uint_as_float(tfu(v)); }

__device__ __forceinline__ void mma_tf32(float* c, const uint32_t* a, float2 b) {
    asm volatile(
        "mma.sync.aligned.m16n8k8.row.col.f32.tf32.tf32.f32 "
        "{%0,%1,%2,%3}, {%4,%5,%6,%7}, {%8,%9}, {%0,%1,%2,%3};"
        : "+f"(c[0]), "+f"(c[1]), "+f"(c[2]), "+f"(c[3])
        : "r"(a[0]), "r"(a[1]), "r"(a[2]), "r"(a[3]),
          "r"(__float_as_uint(b.x)), "r"(__float_as_uint(b.y)));
}

// ---------------------------------------------------------------------------
// tf32 tensor-core GEMM (unchanged)
// ---------------------------------------------------------------------------
#define TG_SMEM (2 * 8192 * 4)

template<int MODE>
__global__ void __launch_bounds__(256) tgemm(const float* __restrict__ A,
                                             const float* __restrict__ W,
                                             float* __restrict__ C,
                                             int M, int N, int K)
{
    extern __shared__ float smf[];
    const int tid = threadIdx.x;
    const int wid = tid >> 5, lane = tid & 31;
    const int wm = wid & 1, wn = wid >> 1;
    const int bm = blockIdx.y * 128, bn = blockIdx.x * 128;

    float acc[4][4][4];
#pragma unroll
    for (int i = 0; i < 4; i++)
#pragma unroll
        for (int j = 0; j < 4; j++)
#pragma unroll
            for (int r = 0; r < 4; r++) acc[i][j][r] = 0.f;

    const int KIT = K / 32;

    int rowv[4], c4v[4], abase[4], bbase[4];
#pragma unroll
    for (int i = 0; i < 4; i++) {
        int idx = tid + i * 256;
        int r = idx >> 3, c = idx & 7;
        rowv[i] = r; c4v[i] = c;
        int mt = r >> 4, r16 = r & 15, ks = c >> 1;
        int rega = (r16 >> 3) + ((c & 1) << 1);
        abase[i] = ((mt * 4 + ks) * 32 + (r16 & 7) * 4) * 4 + rega;
        int nt = r >> 3, nn = r & 7;
        int regb = c & 1;
        bbase[i] = ((nt * 4 + ks) * 32 + nn * 4) * 2 + regb;
    }

    {
        float* da = smf;
        float* db = smf + 4096;
#pragma unroll
        for (int i = 0; i < 4; i++) {
            const float4 va = *(const float4*)(A + (size_t)(bm + rowv[i]) * K + c4v[i] * 4);
            const float4 vb = *(const float4*)(W + (size_t)(bn + rowv[i]) * K + c4v[i] * 4);
            da[abase[i] + 0]  = f2tf32f(va.x);
            da[abase[i] + 4]  = f2tf32f(va.y);
            da[abase[i] + 8]  = f2tf32f(va.z);
            da[abase[i] + 12] = f2tf32f(va.w);
            db[bbase[i] + 0]  = f2tf32f(vb.x);
            db[bbase[i] + 2]  = f2tf32f(vb.y);
            db[bbase[i] + 4]  = f2tf32f(vb.z);
            db[bbase[i] + 6]  = f2tf32f(vb.w);
        }
    }
    __syncthreads();

    for (int it = 0; it < KIT; it++) {
        float4 pa[4], pb[4];
        const bool pref = (it + 1 < KIT);
        if (pref) {
            const int ko = (it + 1) * 32;
#pragma unroll
            for (int i = 0; i < 4; i++) {
                pa[i] = *(const float4*)(A + (size_t)(bm + rowv[i]) * K + ko + c4v[i] * 4);
                pb[i] = *(const float4*)(W + (size_t)(bn + rowv[i]) * K + ko + c4v[i] * 4);
            }
        }

        const float* sa = smf + (it & 1) * 8192;
        const float* sb = sa + 4096;

#pragma unroll
        for (int ks = 0; ks < 4; ks++) {
            uint32_t af[4][4], bf[4][2];
#pragma unroll
            for (int i = 0; i < 4; i++) {
                const int mt = wm * 4 + i;
                const float4 v = *(const float4*)(sa + ((mt * 4 + ks) * 32 + lane) * 4);
                af[i][0] = __float_as_uint(v.x); af[i][1] = __float_as_uint(v.y);
                af[i][2] = __float_as_uint(v.z); af[i][3] = __float_as_uint(v.w);
            }
#pragma unroll
            for (int j = 0; j < 4; j++) {
                const int nt = wn * 4 + j;
                const float2 v = *(const float2*)(sb + ((nt * 4 + ks) * 32 + lane) * 2);
                bf[j][0] = __float_as_uint(v.x); bf[j][1] = __float_as_uint(v.y);
            }
#pragma unroll
            for (int i = 0; i < 4; i++)
#pragma unroll
                for (int j = 0; j < 4; j++) {
                    asm volatile(
                        "mma.sync.aligned.m16n8k8.row.col.f32.tf32.tf32.f32 "
                        "{%0,%1,%2,%3}, {%4,%5,%6,%7}, {%8,%9}, {%0,%1,%2,%3};"
                        : "+f"(acc[i][j][0]), "+f"(acc[i][j][1]),
                          "+f"(acc[i][j][2]), "+f"(acc[i][j][3])
                        : "r"(af[i][0]), "r"(af[i][1]), "r"(af[i][2]), "r"(af[i][3]),
                          "r"(bf[j][0]), "r"(bf[j][1]));
                }
        }

        if (pref) {
            float* da = smf + ((it + 1) & 1) * 8192;
            float* db = da + 4096;
#pragma unroll
            for (int i = 0; i < 4; i++) {
                da[abase[i] + 0]  = f2tf32f(pa[i].x);
                da[abase[i] + 4]  = f2tf32f(pa[i].y);
                da[abase[i] + 8]  = f2tf32f(pa[i].z);
                da[abase[i] + 12] = f2tf32f(pa[i].w);
                db[bbase[i] + 0]  = f2tf32f(pb[i].x);
                db[bbase[i] + 2]  = f2tf32f(pb[i].y);
                db[bbase[i] + 4]  = f2tf32f(pb[i].z);
                db[bbase[i] + 6]  = f2tf32f(pb[i].w);
            }
        }
        __syncthreads();
    }

#pragma unroll
    for (int i = 0; i < 4; i++) {
#pragma unroll
        for (int j = 0; j < 4; j++) {
            const int m0 = bm + wm * 64 + i * 16 + (lane >> 2);
            const int n0 = bn + wn * 32 + j * 8 + (lane & 3) * 2;
            float2 lo = { acc[i][j][0], acc[i][j][1] };
            float2 hi = { acc[i][j][2], acc[i][j][3] };
            if (MODE == 0) {
                *(float2*)(C + (size_t)m0 * N + n0) = lo;
                *(float2*)(C + (size_t)(m0 + 8) * N + n0) = hi;
            } else {
                const int h = n0 >> 6, d = n0 & 63;
                const int b0 = m0 >> 11, s0 = m0 & (SEQ - 1);
                *(float2*)(C + ((size_t)((b0*NH + h)*SEQ + s0) << 6) + d) = lo;
                const int m1 = m0 + 8;
                const int b1 = m1 >> 11, s1 = m1 & (SEQ - 1);
                *(float2*)(C + ((size_t)((b1*NH + h)*SEQ + s1) << 6) + d) = hi;
            }
        }
    }
}

// ---------------------------------------------------------------------------
// Tensor-core flash attention, double-buffered K/V with LDG prefetch.
// Block: 128 q-rows x 1 head, 8 warps. BK=64. grid(16, 64), 256 threads.
// SMEM: Qs[128][68] (reused as per-warp P), Kf[2][4096], Vf[2][4096].
// exp in base-2 domain: Q pre-scaled by 0.125*log2(e).
// ---------------------------------------------------------------------------
#define QLD 68
#define ATT_SMEM ((128*QLD + 2*4096 + 2*4096) * 4)

__global__ void __launch_bounds__(256) attn_tc(const float* __restrict__ Qg,
                                               const float* __restrict__ Kg,
                                               const float* __restrict__ Vg,
                                               float* __restrict__ Out)
{
    extern __shared__ float sm[];
    float* Qs = sm;                    // 128 x 68 (reused as P)
    float* KfB = sm + 128*QLD;         // 2 x 4096
    float* VfB = KfB + 2*4096;         // 2 x 4096

    const int qt = (SEQ/128 - 1) - blockIdx.x;
    const int bh = blockIdx.y;
    const int b = bh >> 4, h = bh & 15;
    const int tid = threadIdx.x, w = tid >> 5, lane = tid & 31;
    const int g = lane >> 2, t = lane & 3;

    const float* Qb = Qg + (size_t)(bh*SEQ + qt*128)*HD;
    const float* Kb = Kg + (size_t)bh*SEQ*HD;
    const float* Vb = Vg + (size_t)bh*SEQ*HD;

    // per-thread K/V gmem->frag scatter geometry
    int keyv[4], d0v[4];
#pragma unroll
    for (int i = 0; i < 4; i++) {
        int f4 = tid + i*256;
        keyv[i] = f4 >> 4;
        d0v[i]  = (f4 & 15) * 4;
    }

    // stage Q coalesced
    for (int i = tid; i < 128*16; i += 256) {
        int r = i >> 4, c4 = (i & 15) << 2;
        float4 v = *(const float4*)(Qb + r*HD + c4);
        float* p = Qs + r*QLD + c4;
        p[0]=v.x; p[1]=v.y; p[2]=v.z; p[3]=v.w;
    }
    __syncthreads();

    // Q A-frags, pre-scaled by (1/8) * log2(e)
    uint32_t qf[8][4];
    {
        const float sc = 0.125f * 1.44269504088896340736f;
        const int r0 = w*16 + g;
#pragma unroll
        for (int ks = 0; ks < 8; ks++) {
            int col = ks*8 + t;
            qf[ks][0] = tfu(Qs[r0*QLD + col] * sc);
            qf[ks][1] = tfu(Qs[(r0+8)*QLD + col] * sc);
            qf[ks][2] = tfu(Qs[r0*QLD + col + 4] * sc);
            qf[ks][3] = tfu(Qs[(r0+8)*QLD + col + 4] * sc);
        }
    }
    __syncthreads();      // Qs now free -> per-warp P buffers

    float* Pw = Qs + w*1024;

    float mrow[2] = { -1e30f, -1e30f };
    float lrow[2] = { 0.f, 0.f };
    float oacc[8][4];
#pragma unroll
    for (int i = 0; i < 8; i++)
#pragma unroll
        for (int r = 0; r < 4; r++) oacc[i][r] = 0.f;

    const int nkt = 2*qt + 2;

    // ---- prologue: load tile 0 into buffer 0 ----
    {
        const float* Kt = Kb;
        const float* Vt = Vb;
#pragma unroll
        for (int i = 0; i < 4; i++) {
            const int key = keyv[i], d0 = d0v[i];
            float4 kv = *(const float4*)(Kt + key*HD + d0);
            float4 vv = *(const float4*)(Vt + key*HD + d0);
            float kvals[4] = { kv.x, kv.y, kv.z, kv.w };
            float vvals[4] = { vv.x, vv.y, vv.z, vv.w };
            const int knt = key >> 3, klb = (key & 7) * 4;
            const int vks = key >> 3, vrg = (key >> 2) & 1, vkl = key & 3;
#pragma unroll
            for (int e = 0; e < 4; e++) {
                int d = d0 + e;
                KfB[((knt*8 + (d >> 3))*32 + klb + (d & 3))*2 + ((d >> 2) & 1)] = f2tf32f(kvals[e]);
                VfB[(((d >> 3)*8 + vks)*32 + (d & 7)*4 + vkl)*2 + vrg] = f2tf32f(vvals[e]);
            }
        }
    }
    __syncthreads();

    for (int kt = 0; kt < nkt; kt++) {
        const bool pref = (kt + 1 < nkt);
        float4 kpf[4], vpf[4];
        if (pref) {
            const float* Kt = Kb + (size_t)(kt+1)*64*HD;
            const float* Vt = Vb + (size_t)(kt+1)*64*HD;
#pragma unroll
            for (int i = 0; i < 4; i++) {
                kpf[i] = *(const float4*)(Kt + keyv[i]*HD + d0v[i]);
                vpf[i] = *(const float4*)(Vt + keyv[i]*HD + d0v[i]);
            }
        }

        const float* Kf = KfB + (kt & 1) * 4096;
        const float* Vf = VfB + (kt & 1) * 4096;

        // ---- S = (Q*scale*log2e) @ K^T ----
        float sacc[8][4];
#pragma unroll
        for (int nt = 0; nt < 8; nt++)
#pragma unroll
            for (int r = 0; r < 4; r++) sacc[nt][r] = 0.f;

#pragma unroll
        for (int ks = 0; ks < 8; ks++)
#pragma unroll
            for (int nt = 0; nt < 8; nt++) {
                float2 bfr = *(const float2*)(Kf + ((nt*8 + ks)*32 + lane)*2);
                mma_tf32(sacc[nt], qf[ks], bfr);
            }

        // ---- causal mask ----
        if (kt >= 2*qt) {
            const int row0 = qt*128 + w*16 + g;
            const int colb = kt*64 + 2*t;
#pragma unroll
            for (int nt = 0; nt < 8; nt++) {
                int c = colb + nt*8;
                if (c     > row0)     sacc[nt][0] = -1e30f;
                if (c + 1 > row0)     sacc[nt][1] = -1e30f;
                if (c     > row0 + 8) sacc[nt][2] = -1e30f;
                if (c + 1 > row0 + 8) sacc[nt][3] = -1e30f;
            }
        }

        // ---- online softmax (base-2) ----
#pragma unroll
        for (int hh = 0; hh < 2; hh++) {
            const int i0 = hh*2;
            float mx = -1e30f;
#pragma unroll
            for (int nt = 0; nt < 8; nt++)
                mx = fmaxf(mx, fmaxf(sacc[nt][i0], sacc[nt][i0+1]));
            mx = fmaxf(mx, __shfl_xor_sync(0xffffffffu, mx, 1));
            mx = fmaxf(mx, __shfl_xor_sync(0xffffffffu, mx, 2));
            float mnew = fmaxf(mrow[hh], mx);
            float corr = exp2f(mrow[hh] - mnew);
            mrow[hh] = mnew;
            float sum = 0.f;
#pragma unroll
            for (int nt = 0; nt < 8; nt++) {
                sacc[nt][i0]   = exp2f(sacc[nt][i0]   - mnew);
                sacc[nt][i0+1] = exp2f(sacc[nt][i0+1] - mnew);
                sum += sacc[nt][i0] + sacc[nt][i0+1];
            }
            sum += __shfl_xor_sync(0xffffffffu, sum, 1);
            sum += __shfl_xor_sync(0xffffffffu, sum, 2);
            lrow[hh] = lrow[hh]*corr + sum;
#pragma unroll
            for (int dt = 0; dt < 8; dt++) {
                oacc[dt][i0]   *= corr;
                oacc[dt][i0+1] *= corr;
            }
        }

        // ---- P -> per-warp smem in A-frag order ----
#pragma unroll
        for (int nt = 0; nt < 8; nt++) {
            int k0 = 2*t, k1 = 2*t + 1;
            int a0 = (nt*32 + g*4 + (k0 & 3))*4 + 2*((k0 >> 2) & 1);
            int a1 = (nt*32 + g*4 + (k1 & 3))*4 + 2*((k1 >> 2) & 1);
            Pw[a0]     = f2tf32f(sacc[nt][0]);
            Pw[a1]     = f2tf32f(sacc[nt][1]);
            Pw[a0 + 1] = f2tf32f(sacc[nt][2]);
            Pw[a1 + 1] = f2tf32f(sacc[nt][3]);
        }
        __syncwarp();

        // ---- O += P @ V ----
#pragma unroll
        for (int ks = 0; ks < 8; ks++) {
            float4 p4 = *(const float4*)(Pw + (ks*32 + g*4 + t)*4);
            uint32_t pf[4] = { __float_as_uint(p4.x), __float_as_uint(p4.y),
                               __float_as_uint(p4.z), __float_as_uint(p4.w) };
#pragma unroll
            for (int dt = 0; dt < 8; dt++) {
                float2 bfr = *(const float2*)(Vf + ((dt*8 + ks)*32 + lane)*2);
                mma_tf32(oacc[dt], pf, bfr);
            }
        }

        // ---- STS prefetched tile into other buffer ----
        if (pref) {
            float* Kd = KfB + ((kt+1) & 1) * 4096;
            float* Vd = VfB + ((kt+1) & 1) * 4096;
#pragma unroll
            for (int i = 0; i < 4; i++) {
                const int key = keyv[i], d0 = d0v[i];
                float kvals[4] = { kpf[i].x, kpf[i].y, kpf[i].z, kpf[i].w };
                float vvals[4] = { vpf[i].x, vpf[i].y, vpf[i].z, vpf[i].w };
                const int knt = key >> 3, klb = (key & 7) * 4;
                const int vks = key >> 3, vrg = (key >> 2) & 1, vkl = key & 3;
#pragma unroll
                for (int e = 0; e < 4; e++) {
                    int d = d0 + e;
                    Kd[((knt*8 + (d >> 3))*32 + klb + (d & 3))*2 + ((d >> 2) & 1)] = f2tf32f(kvals[e]);
                    Vd[(((d >> 3)*8 + vks)*32 + (d & 7)*4 + vkl)*2 + vrg] = f2tf32f(vvals[e]);
                }
            }
        }
        __syncthreads();   // single barrier per iteration
    }

    // ---- epilogue ----
    const float inv0 = 1.0f / lrow[0];
    const float inv1 = 1.0f / lrow[1];
    const int row0 = qt*128 + w*16 + g;
#pragma unroll
    for (int dt = 0; dt < 8; dt++) {
        const int col = h*64 + dt*8 + 2*t;
        float2 lo = { oacc[dt][0]*inv0, oacc[dt][1]*inv0 };
        float2 hi = { oacc[dt][2]*inv1, oacc[dt][3]*inv1 };
        *(float2*)(Out + (size_t)(b*SEQ + row0)*EMB + col) = lo;
        *(float2*)(Out + (size_t)(b*SEQ + row0 + 8)*EMB + col) = hi;
    }
}

extern "C" void kernel_launch(void* const* d_in, const int* in_sizes, int n_in,
                              void* d_out, int out_size)
{
    const float* x  = (const float*)d_in[0];
    const float* Wq = (const float*)d_in[1];
    const float* Wk = (const float*)d_in[2];
    const float* Wv = (const float*)d_in[3];
    const float* Wo = (const float*)d_in[4];
    float* out = (float*)d_out;

    float *q, *k, *v, *m;
    cudaGetSymbolAddress((void**)&q, g_q);
    cudaGetSymbolAddress((void**)&k, g_k);
    cudaGetSymbolAddress((void**)&v, g_v);
    cudaGetSymbolAddress((void**)&m, g_m);

    const int M = BSZ*SEQ, N = EMB, K = EMB;
    dim3 ggrid(N/128, M/128);

    cudaFuncSetAttribute(tgemm<0>, cudaFuncAttributeMaxDynamicSharedMemorySize, TG_SMEM);
    cudaFuncSetAttribute(tgemm<1>, cudaFuncAttributeMaxDynamicSharedMemorySize, TG_SMEM);
    cudaFuncSetAttribute(attn_tc, cudaFuncAttributeMaxDynamicSharedMemorySize, ATT_SMEM);

    tgemm<1><<<ggrid, 256, TG_SMEM>>>(x, Wq, q, M, N, K);
    tgemm<1><<<ggrid, 256, TG_SMEM>>>(x, Wk, k, M, N, K);
    tgemm<1><<<ggrid, 256, TG_SMEM>>>(x, Wv, v, M, N, K);

    attn_tc<<<dim3(SEQ/128, BH), 256, ATT_SMEM>>>(q, k, v, m);

    tgemm<0><<<ggrid, 256, TG_SMEM>>>(m, Wo, out, M, N, K);
}

// round 8
// speedup vs baseline: 2.8531x; 1.3095x over previous
#include <cuda_runtime.h>
#include <cuda_fp16.h>
#include <cstdint>

#define EMB  1024
#define NH   16
#define HD   64
#define BSZ  4
#define SEQ  2048
#define BH   (BSZ*NH)

__device__ float g_q[BH*SEQ*HD];
__device__ float g_k[BH*SEQ*HD];
__device__ float g_v[BH*SEQ*HD];
__device__ float g_m[BSZ*SEQ*EMB];

__device__ __forceinline__ uint32_t tfu(float v) {
    uint32_t u;
    asm("cvt.rna.tf32.f32 %0, %1;" : "=r"(u) : "f"(v));
    return u;
}
__device__ __forceinline__ float f2tf32f(float v) { return __uint_as_float(tfu(v)); }

__device__ __forceinline__ uint32_t h2u(__half2 h) {
    union { __half2 h; uint32_t u; } c; c.h = h; return c.u;
}

__device__ __forceinline__ void mma_f16(float* c, const uint32_t* a, uint2 b) {
    asm volatile(
        "mma.sync.aligned.m16n8k16.row.col.f32.f16.f16.f32 "
        "{%0,%1,%2,%3}, {%4,%5,%6,%7}, {%8,%9}, {%0,%1,%2,%3};"
        : "+f"(c[0]), "+f"(c[1]), "+f"(c[2]), "+f"(c[3])
        : "r"(a[0]), "r"(a[1]), "r"(a[2]), "r"(a[3]),
          "r"(b.x), "r"(b.y));
}

// ---------------------------------------------------------------------------
// tf32 tensor-core GEMM (unchanged)
// ---------------------------------------------------------------------------
#define TG_SMEM (2 * 8192 * 4)

template<int MODE>
__global__ void __launch_bounds__(256) tgemm(const float* __restrict__ A,
                                             const float* __restrict__ W,
                                             float* __restrict__ C,
                                             int M, int N, int K)
{
    extern __shared__ float smf[];
    const int tid = threadIdx.x;
    const int wid = tid >> 5, lane = tid & 31;
    const int wm = wid & 1, wn = wid >> 1;
    const int bm = blockIdx.y * 128, bn = blockIdx.x * 128;

    float acc[4][4][4];
#pragma unroll
    for (int i = 0; i < 4; i++)
#pragma unroll
        for (int j = 0; j < 4; j++)
#pragma unroll
            for (int r = 0; r < 4; r++) acc[i][j][r] = 0.f;

    const int KIT = K / 32;

    int rowv[4], c4v[4], abase[4], bbase[4];
#pragma unroll
    for (int i = 0; i < 4; i++) {
        int idx = tid + i * 256;
        int r = idx >> 3, c = idx & 7;
        rowv[i] = r; c4v[i] = c;
        int mt = r >> 4, r16 = r & 15, ks = c >> 1;
        int rega = (r16 >> 3) + ((c & 1) << 1);
        abase[i] = ((mt * 4 + ks) * 32 + (r16 & 7) * 4) * 4 + rega;
        int nt = r >> 3, nn = r & 7;
        int regb = c & 1;
        bbase[i] = ((nt * 4 + ks) * 32 + nn * 4) * 2 + regb;
    }

    {
        float* da = smf;
        float* db = smf + 4096;
#pragma unroll
        for (int i = 0; i < 4; i++) {
            const float4 va = *(const float4*)(A + (size_t)(bm + rowv[i]) * K + c4v[i] * 4);
            const float4 vb = *(const float4*)(W + (size_t)(bn + rowv[i]) * K + c4v[i] * 4);
            da[abase[i] + 0]  = f2tf32f(va.x);
            da[abase[i] + 4]  = f2tf32f(va.y);
            da[abase[i] + 8]  = f2tf32f(va.z);
            da[abase[i] + 12] = f2tf32f(va.w);
            db[bbase[i] + 0]  = f2tf32f(vb.x);
            db[bbase[i] + 2]  = f2tf32f(vb.y);
            db[bbase[i] + 4]  = f2tf32f(vb.z);
            db[bbase[i] + 6]  = f2tf32f(vb.w);
        }
    }
    __syncthreads();

    for (int it = 0; it < KIT; it++) {
        float4 pa[4], pb[4];
        const bool pref = (it + 1 < KIT);
        if (pref) {
            const int ko = (it + 1) * 32;
#pragma unroll
            for (int i = 0; i < 4; i++) {
                pa[i] = *(const float4*)(A + (size_t)(bm + rowv[i]) * K + ko + c4v[i] * 4);
                pb[i] = *(const float4*)(W + (size_t)(bn + rowv[i]) * K + ko + c4v[i] * 4);
            }
        }

        const float* sa = smf + (it & 1) * 8192;
        const float* sb = sa + 4096;

#pragma unroll
        for (int ks = 0; ks < 4; ks++) {
            uint32_t af[4][4], bf[4][2];
#pragma unroll
            for (int i = 0; i < 4; i++) {
                const int mt = wm * 4 + i;
                const float4 v = *(const float4*)(sa + ((mt * 4 + ks) * 32 + lane) * 4);
                af[i][0] = __float_as_uint(v.x); af[i][1] = __float_as_uint(v.y);
                af[i][2] = __float_as_uint(v.z); af[i][3] = __float_as_uint(v.w);
            }
#pragma unroll
            for (int j = 0; j < 4; j++) {
                const int nt = wn * 4 + j;
                const float2 v = *(const float2*)(sb + ((nt * 4 + ks) * 32 + lane) * 2);
                bf[j][0] = __float_as_uint(v.x); bf[j][1] = __float_as_uint(v.y);
            }
#pragma unroll
            for (int i = 0; i < 4; i++)
#pragma unroll
                for (int j = 0; j < 4; j++) {
                    asm volatile(
                        "mma.sync.aligned.m16n8k8.row.col.f32.tf32.tf32.f32 "
                        "{%0,%1,%2,%3}, {%4,%5,%6,%7}, {%8,%9}, {%0,%1,%2,%3};"
                        : "+f"(acc[i][j][0]), "+f"(acc[i][j][1]),
                          "+f"(acc[i][j][2]), "+f"(acc[i][j][3])
                        : "r"(af[i][0]), "r"(af[i][1]), "r"(af[i][2]), "r"(af[i][3]),
                          "r"(bf[j][0]), "r"(bf[j][1]));
                }
        }

        if (pref) {
            float* da = smf + ((it + 1) & 1) * 8192;
            float* db = da + 4096;
#pragma unroll
            for (int i = 0; i < 4; i++) {
                da[abase[i] + 0]  = f2tf32f(pa[i].x);
                da[abase[i] + 4]  = f2tf32f(pa[i].y);
                da[abase[i] + 8]  = f2tf32f(pa[i].z);
                da[abase[i] + 12] = f2tf32f(pa[i].w);
                db[bbase[i] + 0]  = f2tf32f(pb[i].x);
                db[bbase[i] + 2]  = f2tf32f(pb[i].y);
                db[bbase[i] + 4]  = f2tf32f(pb[i].z);
                db[bbase[i] + 6]  = f2tf32f(pb[i].w);
            }
        }
        __syncthreads();
    }

#pragma unroll
    for (int i = 0; i < 4; i++) {
#pragma unroll
        for (int j = 0; j < 4; j++) {
            const int m0 = bm + wm * 64 + i * 16 + (lane >> 2);
            const int n0 = bn + wn * 32 + j * 8 + (lane & 3) * 2;
            float2 lo = { acc[i][j][0], acc[i][j][1] };
            float2 hi = { acc[i][j][2], acc[i][j][3] };
            if (MODE == 0) {
                *(float2*)(C + (size_t)m0 * N + n0) = lo;
                *(float2*)(C + (size_t)(m0 + 8) * N + n0) = hi;
            } else {
                const int h = n0 >> 6, d = n0 & 63;
                const int b0 = m0 >> 11, s0 = m0 & (SEQ - 1);
                *(float2*)(C + ((size_t)((b0*NH + h)*SEQ + s0) << 6) + d) = lo;
                const int m1 = m0 + 8;
                const int b1 = m1 >> 11, s1 = m1 & (SEQ - 1);
                *(float2*)(C + ((size_t)((b1*NH + h)*SEQ + s1) << 6) + d) = hi;
            }
        }
    }
}

// ---------------------------------------------------------------------------
// fp16 tensor-core flash attention (m16n8k16), double-buffered K/V.
// Block: 128 q-rows x 1 head, 8 warps. BK=64. grid(16, 64), 256 threads.
// K/V smem: fragment-order half arrays, padded frag groups (136 halves) +
// XOR-swizzled t index => conflict-free LDS.64 frag loads, ~2-way STS.
// P stays in registers (fp16 C-frag == A-frag layout).
// ---------------------------------------------------------------------------
#define QLD 68
#define KVH 4352                      // halves per K or V buffer (32 frag * 136)
#define ATT_SMEM (128*QLD*4 + 4*KVH*2)

__device__ __forceinline__ void store_kv(__half* Kd, __half* Vd,
                                         int key, int d0, float4 kv, float4 vv)
{
    // K frag: B[k=d][n=key]
    const int nt = key >> 3, gk = key & 7, ksK = d0 >> 4;
    const int t0 = (d0 >> 1) & 3, regK = (d0 >> 3) & 1, swK = ksK & 3;
    __half* kb = Kd + (nt*4 + ksK)*136 + gk*16 + regK*2;
    *(__half2*)(kb + ((t0    ) ^ swK)*4) = __floats2half2_rn(kv.x, kv.y);
    *(__half2*)(kb + ((t0 + 1) ^ swK)*4) = __floats2half2_rn(kv.z, kv.w);

    // V frag: B[k=key][n=d]
    const int ksV = key >> 4, tV = (key >> 1) & 3, regV = (key >> 3) & 1, loV = key & 1;
    const int dt = d0 >> 3, gv0 = d0 & 7;
    const int tV2 = tV ^ (dt & 3);
    __half* vb = Vd + (dt*4 + ksV)*136 + gv0*16 + tV2*4 + regV*2 + loV;
    vb[0]  = __float2half_rn(vv.x);
    vb[16] = __float2half_rn(vv.y);
    vb[32] = __float2half_rn(vv.z);
    vb[48] = __float2half_rn(vv.w);
}

__global__ void __launch_bounds__(256) attn_tc(const float* __restrict__ Qg,
                                               const float* __restrict__ Kg,
                                               const float* __restrict__ Vg,
                                               float* __restrict__ Out)
{
    extern __shared__ float sm[];
    float* Qs = sm;                              // 128 x 68 fp32
    __half* KfB = (__half*)(sm + 128*QLD);       // 2 x KVH halves
    __half* VfB = KfB + 2*KVH;                   // 2 x KVH halves

    const int qt = (SEQ/128 - 1) - blockIdx.x;
    const int bh = blockIdx.y;
    const int b = bh >> 4, h = bh & 15;
    const int tid = threadIdx.x, w = tid >> 5, lane = tid & 31;
    const int g = lane >> 2, t = lane & 3;

    const float* Qb = Qg + (size_t)(bh*SEQ + qt*128)*HD;
    const float* Kb = Kg + (size_t)bh*SEQ*HD;
    const float* Vb = Vg + (size_t)bh*SEQ*HD;

    int keyv[4], d0v[4];
#pragma unroll
    for (int i = 0; i < 4; i++) {
        int f4 = tid + i*256;
        keyv[i] = f4 >> 4;
        d0v[i]  = (f4 & 15) * 4;
    }

    // stage Q coalesced
    for (int i = tid; i < 128*16; i += 256) {
        int r = i >> 4, c4 = (i & 15) << 2;
        float4 v = *(const float4*)(Qb + r*HD + c4);
        float* p = Qs + r*QLD + c4;
        p[0]=v.x; p[1]=v.y; p[2]=v.z; p[3]=v.w;
    }
    __syncthreads();

    // Q A-frags (fp16 half2), pre-scaled by (1/8)*log2(e)
    uint32_t qf[4][4];
    {
        const float sc = 0.125f * 1.44269504088896340736f;
        const int r0 = w*16 + g;
#pragma unroll
        for (int ks = 0; ks < 4; ks++) {
            const int c0 = ks*16 + 2*t;
            qf[ks][0] = h2u(__floats2half2_rn(Qs[r0*QLD + c0]*sc,     Qs[r0*QLD + c0+1]*sc));
            qf[ks][1] = h2u(__floats2half2_rn(Qs[(r0+8)*QLD + c0]*sc, Qs[(r0+8)*QLD + c0+1]*sc));
            qf[ks][2] = h2u(__floats2half2_rn(Qs[r0*QLD + c0+8]*sc,   Qs[r0*QLD + c0+9]*sc));
            qf[ks][3] = h2u(__floats2half2_rn(Qs[(r0+8)*QLD + c0+8]*sc, Qs[(r0+8)*QLD + c0+9]*sc));
        }
    }

    float mrow[2] = { -1e30f, -1e30f };
    float lrow[2] = { 0.f, 0.f };
    float oacc[8][4];
#pragma unroll
    for (int i = 0; i < 8; i++)
#pragma unroll
        for (int r = 0; r < 4; r++) oacc[i][r] = 0.f;

    const int nkt = 2*qt + 2;

    // prologue: tile 0 -> buffer 0
#pragma unroll
    for (int i = 0; i < 4; i++) {
        float4 kv = *(const float4*)(Kb + keyv[i]*HD + d0v[i]);
        float4 vv = *(const float4*)(Vb + keyv[i]*HD + d0v[i]);
        store_kv(KfB, VfB, keyv[i], d0v[i], kv, vv);
    }
    __syncthreads();

    for (int kt = 0; kt < nkt; kt++) {
        const bool pref = (kt + 1 < nkt);
        float4 kpf[4], vpf[4];
        if (pref) {
            const float* Kt = Kb + (size_t)(kt+1)*64*HD;
            const float* Vt = Vb + (size_t)(kt+1)*64*HD;
#pragma unroll
            for (int i = 0; i < 4; i++) {
                kpf[i] = *(const float4*)(Kt + keyv[i]*HD + d0v[i]);
                vpf[i] = *(const float4*)(Vt + keyv[i]*HD + d0v[i]);
            }
        }

        const __half* Kf = KfB + (kt & 1) * KVH;
        const __half* Vf = VfB + (kt & 1) * KVH;

        // ---- S = (Q*scale*log2e) @ K^T ----
        float sacc[8][4];
#pragma unroll
        for (int nt = 0; nt < 8; nt++)
#pragma unroll
            for (int r = 0; r < 4; r++) sacc[nt][r] = 0.f;

#pragma unroll
        for (int ks = 0; ks < 4; ks++) {
            const int tp = (t ^ (ks & 3)) * 4;
#pragma unroll
            for (int nt = 0; nt < 8; nt++) {
                uint2 bfr = *(const uint2*)(Kf + (nt*4 + ks)*136 + g*16 + tp);
                mma_f16(sacc[nt], qf[ks], bfr);
            }
        }

        // ---- causal mask ----
        if (kt >= 2*qt) {
            const int row0 = qt*128 + w*16 + g;
            const int colb = kt*64 + 2*t;
#pragma unroll
            for (int nt = 0; nt < 8; nt++) {
                int c = colb + nt*8;
                if (c     > row0)     sacc[nt][0] = -1e30f;
                if (c + 1 > row0)     sacc[nt][1] = -1e30f;
                if (c     > row0 + 8) sacc[nt][2] = -1e30f;
                if (c + 1 > row0 + 8) sacc[nt][3] = -1e30f;
            }
        }

        // ---- online softmax (base-2) ----
#pragma unroll
        for (int hh = 0; hh < 2; hh++) {
            const int i0 = hh*2;
            float mx = -1e30f;
#pragma unroll
            for (int nt = 0; nt < 8; nt++)
                mx = fmaxf(mx, fmaxf(sacc[nt][i0], sacc[nt][i0+1]));
            mx = fmaxf(mx, __shfl_xor_sync(0xffffffffu, mx, 1));
            mx = fmaxf(mx, __shfl_xor_sync(0xffffffffu, mx, 2));
            float mnew = fmaxf(mrow[hh], mx);
            float corr = exp2f(mrow[hh] - mnew);
            mrow[hh] = mnew;
            float sum = 0.f;
#pragma unroll
            for (int nt = 0; nt < 8; nt++) {
                sacc[nt][i0]   = exp2f(sacc[nt][i0]   - mnew);
                sacc[nt][i0+1] = exp2f(sacc[nt][i0+1] - mnew);
                sum += sacc[nt][i0] + sacc[nt][i0+1];
            }
            sum += __shfl_xor_sync(0xffffffffu, sum, 1);
            sum += __shfl_xor_sync(0xffffffffu, sum, 2);
            lrow[hh] = lrow[hh]*corr + sum;
#pragma unroll
            for (int dt = 0; dt < 8; dt++) {
                oacc[dt][i0]   *= corr;
                oacc[dt][i0+1] *= corr;
            }
        }

        // ---- O += P @ V  (P straight from registers: C-frag == A-frag) ----
#pragma unroll
        for (int ks = 0; ks < 4; ks++) {
            uint32_t pf[4];
            pf[0] = h2u(__floats2half2_rn(sacc[2*ks][0],   sacc[2*ks][1]));
            pf[1] = h2u(__floats2half2_rn(sacc[2*ks][2],   sacc[2*ks][3]));
            pf[2] = h2u(__floats2half2_rn(sacc[2*ks+1][0], sacc[2*ks+1][1]));
            pf[3] = h2u(__floats2half2_rn(sacc[2*ks+1][2], sacc[2*ks+1][3]));
#pragma unroll
            for (int dt = 0; dt < 8; dt++) {
                uint2 bfr = *(const uint2*)(Vf + (dt*4 + ks)*136 + g*16 + (t ^ (dt & 3))*4);
                mma_f16(oacc[dt], pf, bfr);
            }
        }

        // ---- STS prefetched tile into other buffer ----
        if (pref) {
            __half* Kd = KfB + ((kt+1) & 1) * KVH;
            __half* Vd = VfB + ((kt+1) & 1) * KVH;
#pragma unroll
            for (int i = 0; i < 4; i++)
                store_kv(Kd, Vd, keyv[i], d0v[i], kpf[i], vpf[i]);
        }
        __syncthreads();
    }

    // ---- epilogue ----
    const float inv0 = 1.0f / lrow[0];
    const float inv1 = 1.0f / lrow[1];
    const int row0 = qt*128 + w*16 + g;
#pragma unroll
    for (int dt = 0; dt < 8; dt++) {
        const int col = h*64 + dt*8 + 2*t;
        float2 lo = { oacc[dt][0]*inv0, oacc[dt][1]*inv0 };
        float2 hi = { oacc[dt][2]*inv1, oacc[dt][3]*inv1 };
        *(float2*)(Out + (size_t)(b*SEQ + row0)*EMB + col) = lo;
        *(float2*)(Out + (size_t)(b*SEQ + row0 + 8)*EMB + col) = hi;
    }
}

extern "C" void kernel_launch(void* const* d_in, const int* in_sizes, int n_in,
                              void* d_out, int out_size)
{
    const float* x  = (const float*)d_in[0];
    const float* Wq = (const float*)d_in[1];
    const float* Wk = (const float*)d_in[2];
    const float* Wv = (const float*)d_in[3];
    const float* Wo = (const float*)d_in[4];
    float* out = (float*)d_out;

    float *q, *k, *v, *m;
    cudaGetSymbolAddress((void**)&q, g_q);
    cudaGetSymbolAddress((void**)&k, g_k);
    cudaGetSymbolAddress((void**)&v, g_v);
    cudaGetSymbolAddress((void**)&m, g_m);

    const int M = BSZ*SEQ, N = EMB, K = EMB;
    dim3 ggrid(N/128, M/128);

    cudaFuncSetAttribute(tgemm<0>, cudaFuncAttributeMaxDynamicSharedMemorySize, TG_SMEM);
    cudaFuncSetAttribute(tgemm<1>, cudaFuncAttributeMaxDynamicSharedMemorySize, TG_SMEM);
    cudaFuncSetAttribute(attn_tc, cudaFuncAttributeMaxDynamicSharedMemorySize, ATT_SMEM);

    tgemm<1><<<ggrid, 256, TG_SMEM>>>(x, Wq, q, M, N, K);
    tgemm<1><<<ggrid, 256, TG_SMEM>>>(x, Wk, k, M, N, K);
    tgemm<1><<<ggrid, 256, TG_SMEM>>>(x, Wv, v, M, N, K);

    attn_tc<<<dim3(SEQ/128, BH), 256, ATT_SMEM>>>(q, k, v, m);

    tgemm<0><<<ggrid, 256, TG_SMEM>>>(m, Wo, out, M, N, K);
}

// round 10
// speedup vs baseline: 3.9038x; 1.3683x over previous
#include <cuda_runtime.h>
#include <cuda_fp16.h>
#include <cstdint>

#define EMB  1024
#define NH   16
#define HD   64
#define BSZ  4
#define SEQ  2048
#define BH   (BSZ*NH)

__device__ float g_q[BH*SEQ*HD];
__device__ float g_k[BH*SEQ*HD];
__device__ float g_v[BH*SEQ*HD];
__device__ float g_m[BSZ*SEQ*EMB];

__device__ __forceinline__ uint32_t h2u(__half2 h) {
    union { __half2 h; uint32_t u; } c; c.h = h; return c.u;
}

__device__ __forceinline__ void mma_f16(float* c, const uint32_t* a, uint2 b) {
    asm volatile(
        "mma.sync.aligned.m16n8k16.row.col.f32.f16.f16.f32 "
        "{%0,%1,%2,%3}, {%4,%5,%6,%7}, {%8,%9}, {%0,%1,%2,%3};"
        : "+f"(c[0]), "+f"(c[1]), "+f"(c[2]), "+f"(c[3])
        : "r"(a[0]), "r"(a[1]), "r"(a[2]), "r"(a[3]),
          "r"(b.x), "r"(b.y));
}

// ---------------------------------------------------------------------------
// fp16 tensor-core GEMM (m16n8k16):  C = A[M,K] @ W[N,K]^T
// Block 256 thr = 8 warps (2m x 4n), tile 128x128, K-chunk 32, dbl-buffered.
// SMEM frag order: A frag 32 lanes x 8 halves (LDS.128), B frag 32 x 4 (LDS.64).
// Stage = 8192 halves (16KB); 2 stages.
// MODE 0: C row-major [M,N].  MODE 1: head-split [B,H,S,D].
// ---------------------------------------------------------------------------
#define TG_SMEM (2 * 8192 * 2)

template<int MODE>
__global__ void __launch_bounds__(256) tgemm(const float* __restrict__ A,
                                             const float* __restrict__ W,
                                             float* __restrict__ C,
                                             int M, int N, int K)
{
    extern __shared__ __half smh[];
    const int tid = threadIdx.x;
    const int wid = tid >> 5, lane = tid & 31;
    const int wm = wid & 1, wn = wid >> 1;
    const int bm = blockIdx.y * 128, bn = blockIdx.x * 128;

    float acc[4][4][4];
#pragma unroll
    for (int i = 0; i < 4; i++)
#pragma unroll
        for (int j = 0; j < 4; j++)
#pragma unroll
            for (int r = 0; r < 4; r++) acc[i][j][r] = 0.f;

    const int KIT = K / 32;

    // per-thread scatter geometry (4 float4 items per array per chunk)
    int rowv[4], c4v[4], offA[4], offB[4];
#pragma unroll
    for (int i = 0; i < 4; i++) {
        int idx = tid + i * 256;
        int r = idx >> 3, c = idx & 7;
        rowv[i] = r; c4v[i] = c;
        int ks = c >> 2, khigh = (c >> 1) & 1, t0 = (c & 1) * 2;
        int mt = r >> 4, r16 = r & 15, g = r16 & 7, up = r16 >> 3;
        offA[i] = ((mt*2 + ks)*32 + g*4 + t0)*8 + (up + 2*khigh)*2;
        int nt = r >> 3, gb = r & 7;
        offB[i] = ((nt*2 + ks)*32 + gb*4 + t0)*4 + khigh*2;
    }

    // ---- load chunk 0 ----
    {
        __half* da = smh;
        __half* db = smh + 4096;
#pragma unroll
        for (int i = 0; i < 4; i++) {
            const float4 va = *(const float4*)(A + (size_t)(bm + rowv[i]) * K + c4v[i] * 4);
            const float4 vb = *(const float4*)(W + (size_t)(bn + rowv[i]) * K + c4v[i] * 4);
            *(__half2*)(da + offA[i])     = __floats2half2_rn(va.x, va.y);
            *(__half2*)(da + offA[i] + 8) = __floats2half2_rn(va.z, va.w);
            *(__half2*)(db + offB[i])     = __floats2half2_rn(vb.x, vb.y);
            *(__half2*)(db + offB[i] + 4) = __floats2half2_rn(vb.z, vb.w);
        }
    }
    __syncthreads();

    for (int it = 0; it < KIT; it++) {
        uint32_t pa[4][2][2], pb[4][2][2];   // prefetched, pre-converted half2s
        const bool pref = (it + 1 < KIT);
        if (pref) {
            const int ko = (it + 1) * 32;
#pragma unroll
            for (int i = 0; i < 4; i++) {
                const float4 va = *(const float4*)(A + (size_t)(bm + rowv[i]) * K + ko + c4v[i] * 4);
                const float4 vb = *(const float4*)(W + (size_t)(bn + rowv[i]) * K + ko + c4v[i] * 4);
                pa[i][0][0] = h2u(__floats2half2_rn(va.x, va.y));
                pa[i][0][1] = h2u(__floats2half2_rn(va.z, va.w));
                pb[i][0][0] = h2u(__floats2half2_rn(vb.x, vb.y));
                pb[i][0][1] = h2u(__floats2half2_rn(vb.z, vb.w));
            }
        }

        const __half* sa = smh + (it & 1) * 8192;
        const __half* sb = sa + 4096;

#pragma unroll
        for (int ks = 0; ks < 2; ks++) {
            uint32_t af[4][4]; uint2 bf[4];
#pragma unroll
            for (int i = 0; i < 4; i++) {
                const int mt = wm * 4 + i;
                const uint4 v = *(const uint4*)(sa + ((mt*2 + ks)*32 + lane)*8);
                af[i][0] = v.x; af[i][1] = v.y; af[i][2] = v.z; af[i][3] = v.w;
            }
#pragma unroll
            for (int j = 0; j < 4; j++) {
                const int nt = wn * 4 + j;
                bf[j] = *(const uint2*)(sb + ((nt*2 + ks)*32 + lane)*4);
            }
#pragma unroll
            for (int i = 0; i < 4; i++)
#pragma unroll
                for (int j = 0; j < 4; j++)
                    mma_f16(acc[i][j], af[i], bf[j]);
        }

        if (pref) {
            __half* da = smh + ((it + 1) & 1) * 8192;
            __half* db = da + 4096;
#pragma unroll
            for (int i = 0; i < 4; i++) {
                *(uint32_t*)(da + offA[i])     = pa[i][0][0];
                *(uint32_t*)(da + offA[i] + 8) = pa[i][0][1];
                *(uint32_t*)(db + offB[i])     = pb[i][0][0];
                *(uint32_t*)(db + offB[i] + 4) = pb[i][0][1];
            }
        }
        __syncthreads();
    }

    // epilogue (C frag layout identical to m16n8k8 case)
#pragma unroll
    for (int i = 0; i < 4; i++) {
#pragma unroll
        for (int j = 0; j < 4; j++) {
            const int m0 = bm + wm * 64 + i * 16 + (lane >> 2);
            const int n0 = bn + wn * 32 + j * 8 + (lane & 3) * 2;
            float2 lo = { acc[i][j][0], acc[i][j][1] };
            float2 hi = { acc[i][j][2], acc[i][j][3] };
            if (MODE == 0) {
                *(float2*)(C + (size_t)m0 * N + n0) = lo;
                *(float2*)(C + (size_t)(m0 + 8) * N + n0) = hi;
            } else {
                const int h = n0 >> 6, d = n0 & 63;
                const int b0 = m0 >> 11, s0 = m0 & (SEQ - 1);
                *(float2*)(C + ((size_t)((b0*NH + h)*SEQ + s0) << 6) + d) = lo;
                const int m1 = m0 + 8;
                const int b1 = m1 >> 11, s1 = m1 & (SEQ - 1);
                *(float2*)(C + ((size_t)((b1*NH + h)*SEQ + s1) << 6) + d) = hi;
            }
        }
    }
}

// ---------------------------------------------------------------------------
// fp16 tensor-core flash attention (unchanged from round 7)
// ---------------------------------------------------------------------------
#define QLD 68
#define KVH 4352
#define ATT_SMEM (128*QLD*4 + 4*KVH*2)

__device__ __forceinline__ void store_kv(__half* Kd, __half* Vd,
                                         int key, int d0, float4 kv, float4 vv)
{
    const int nt = key >> 3, gk = key & 7, ksK = d0 >> 4;
    const int t0 = (d0 >> 1) & 3, regK = (d0 >> 3) & 1, swK = ksK & 3;
    __half* kb = Kd + (nt*4 + ksK)*136 + gk*16 + regK*2;
    *(__half2*)(kb + ((t0    ) ^ swK)*4) = __floats2half2_rn(kv.x, kv.y);
    *(__half2*)(kb + ((t0 + 1) ^ swK)*4) = __floats2half2_rn(kv.z, kv.w);

    const int ksV = key >> 4, tV = (key >> 1) & 3, regV = (key >> 3) & 1, loV = key & 1;
    const int dt = d0 >> 3, gv0 = d0 & 7;
    const int tV2 = tV ^ (dt & 3);
    __half* vb = Vd + (dt*4 + ksV)*136 + gv0*16 + tV2*4 + regV*2 + loV;
    vb[0]  = __float2half_rn(vv.x);
    vb[16] = __float2half_rn(vv.y);
    vb[32] = __float2half_rn(vv.z);
    vb[48] = __float2half_rn(vv.w);
}

__global__ void __launch_bounds__(256) attn_tc(const float* __restrict__ Qg,
                                               const float* __restrict__ Kg,
                                               const float* __restrict__ Vg,
                                               float* __restrict__ Out)
{
    extern __shared__ float sm[];
    float* Qs = sm;
    __half* KfB = (__half*)(sm + 128*QLD);
    __half* VfB = KfB + 2*KVH;

    const int qt = (SEQ/128 - 1) - blockIdx.x;
    const int bh = blockIdx.y;
    const int b = bh >> 4, h = bh & 15;
    const int tid = threadIdx.x, w = tid >> 5, lane = tid & 31;
    const int g = lane >> 2, t = lane & 3;

    const float* Qb = Qg + (size_t)(bh*SEQ + qt*128)*HD;
    const float* Kb = Kg + (size_t)bh*SEQ*HD;
    const float* Vb = Vg + (size_t)bh*SEQ*HD;

    int keyv[4], d0v[4];
#pragma unroll
    for (int i = 0; i < 4; i++) {
        int f4 = tid + i*256;
        keyv[i] = f4 >> 4;
        d0v[i]  = (f4 & 15) * 4;
    }

    for (int i = tid; i < 128*16; i += 256) {
        int r = i >> 4, c4 = (i & 15) << 2;
        float4 v = *(const float4*)(Qb + r*HD + c4);
        float* p = Qs + r*QLD + c4;
        p[0]=v.x; p[1]=v.y; p[2]=v.z; p[3]=v.w;
    }
    __syncthreads();

    uint32_t qf[4][4];
    {
        const float sc = 0.125f * 1.44269504088896340736f;
        const int r0 = w*16 + g;
#pragma unroll
        for (int ks = 0; ks < 4; ks++) {
            const int c0 = ks*16 + 2*t;
            qf[ks][0] = h2u(__floats2half2_rn(Qs[r0*QLD + c0]*sc,     Qs[r0*QLD + c0+1]*sc));
            qf[ks][1] = h2u(__floats2half2_rn(Qs[(r0+8)*QLD + c0]*sc, Qs[(r0+8)*QLD + c0+1]*sc));
            qf[ks][2] = h2u(__floats2half2_rn(Qs[r0*QLD + c0+8]*sc,   Qs[r0*QLD + c0+9]*sc));
            qf[ks][3] = h2u(__floats2half2_rn(Qs[(r0+8)*QLD + c0+8]*sc, Qs[(r0+8)*QLD + c0+9]*sc));
        }
    }

    float mrow[2] = { -1e30f, -1e30f };
    float lrow[2] = { 0.f, 0.f };
    float oacc[8][4];
#pragma unroll
    for (int i = 0; i < 8; i++)
#pragma unroll
        for (int r = 0; r < 4; r++) oacc[i][r] = 0.f;

    const int nkt = 2*qt + 2;

#pragma unroll
    for (int i = 0; i < 4; i++) {
        float4 kv = *(const float4*)(Kb + keyv[i]*HD + d0v[i]);
        float4 vv = *(const float4*)(Vb + keyv[i]*HD + d0v[i]);
        store_kv(KfB, VfB, keyv[i], d0v[i], kv, vv);
    }
    __syncthreads();

    for (int kt = 0; kt < nkt; kt++) {
        const bool pref = (kt + 1 < nkt);
        float4 kpf[4], vpf[4];
        if (pref) {
            const float* Kt = Kb + (size_t)(kt+1)*64*HD;
            const float* Vt = Vb + (size_t)(kt+1)*64*HD;
#pragma unroll
            for (int i = 0; i < 4; i++) {
                kpf[i] = *(const float4*)(Kt + keyv[i]*HD + d0v[i]);
                vpf[i] = *(const float4*)(Vt + keyv[i]*HD + d0v[i]);
            }
        }

        const __half* Kf = KfB + (kt & 1) * KVH;
        const __half* Vf = VfB + (kt & 1) * KVH;

        float sacc[8][4];
#pragma unroll
        for (int nt = 0; nt < 8; nt++)
#pragma unroll
            for (int r = 0; r < 4; r++) sacc[nt][r] = 0.f;

#pragma unroll
        for (int ks = 0; ks < 4; ks++) {
            const int tp = (t ^ (ks & 3)) * 4;
#pragma unroll
            for (int nt = 0; nt < 8; nt++) {
                uint2 bfr = *(const uint2*)(Kf + (nt*4 + ks)*136 + g*16 + tp);
                mma_f16(sacc[nt], qf[ks], bfr);
            }
        }

        if (kt >= 2*qt) {
            const int row0 = qt*128 + w*16 + g;
            const int colb = kt*64 + 2*t;
#pragma unroll
            for (int nt = 0; nt < 8; nt++) {
                int c = colb + nt*8;
                if (c     > row0)     sacc[nt][0] = -1e30f;
                if (c + 1 > row0)     sacc[nt][1] = -1e30f;
                if (c     > row0 + 8) sacc[nt][2] = -1e30f;
                if (c + 1 > row0 + 8) sacc[nt][3] = -1e30f;
            }
        }

#pragma unroll
        for (int hh = 0; hh < 2; hh++) {
            const int i0 = hh*2;
            float mx = -1e30f;
#pragma unroll
            for (int nt = 0; nt < 8; nt++)
                mx = fmaxf(mx, fmaxf(sacc[nt][i0], sacc[nt][i0+1]));
            mx = fmaxf(mx, __shfl_xor_sync(0xffffffffu, mx, 1));
            mx = fmaxf(mx, __shfl_xor_sync(0xffffffffu, mx, 2));
            float mnew = fmaxf(mrow[hh], mx);
            float corr = exp2f(mrow[hh] - mnew);
            mrow[hh] = mnew;
            float sum = 0.f;
#pragma unroll
            for (int nt = 0; nt < 8; nt++) {
                sacc[nt][i0]   = exp2f(sacc[nt][i0]   - mnew);
                sacc[nt][i0+1] = exp2f(sacc[nt][i0+1] - mnew);
                sum += sacc[nt][i0] + sacc[nt][i0+1];
            }
            sum += __shfl_xor_sync(0xffffffffu, sum, 1);
            sum += __shfl_xor_sync(0xffffffffu, sum, 2);
            lrow[hh] = lrow[hh]*corr + sum;
#pragma unroll
            for (int dt = 0; dt < 8; dt++) {
                oacc[dt][i0]   *= corr;
                oacc[dt][i0+1] *= corr;
            }
        }

#pragma unroll
        for (int ks = 0; ks < 4; ks++) {
            uint32_t pf[4];
            pf[0] = h2u(__floats2half2_rn(sacc[2*ks][0],   sacc[2*ks][1]));
            pf[1] = h2u(__floats2half2_rn(sacc[2*ks][2],   sacc[2*ks][3]));
            pf[2] = h2u(__floats2half2_rn(sacc[2*ks+1][0], sacc[2*ks+1][1]));
            pf[3] = h2u(__floats2half2_rn(sacc[2*ks+1][2], sacc[2*ks+1][3]));
#pragma unroll
            for (int dt = 0; dt < 8; dt++) {
                uint2 bfr = *(const uint2*)(Vf + (dt*4 + ks)*136 + g*16 + (t ^ (dt & 3))*4);
                mma_f16(oacc[dt], pf, bfr);
            }
        }

        if (pref) {
            __half* Kd = KfB + ((kt+1) & 1) * KVH;
            __half* Vd = VfB + ((kt+1) & 1) * KVH;
#pragma unroll
            for (int i = 0; i < 4; i++)
                store_kv(Kd, Vd, keyv[i], d0v[i], kpf[i], vpf[i]);
        }
        __syncthreads();
    }

    const float inv0 = 1.0f / lrow[0];
    const float inv1 = 1.0f / lrow[1];
    const int row0 = qt*128 + w*16 + g;
#pragma unroll
    for (int dt = 0; dt < 8; dt++) {
        const int col = h*64 + dt*8 + 2*t;
        float2 lo = { oacc[dt][0]*inv0, oacc[dt][1]*inv0 };
        float2 hi = { oacc[dt][2]*inv1, oacc[dt][3]*inv1 };
        *(float2*)(Out + (size_t)(b*SEQ + row0)*EMB + col) = lo;
        *(float2*)(Out + (size_t)(b*SEQ + row0 + 8)*EMB + col) = hi;
    }
}

extern "C" void kernel_launch(void* const* d_in, const int* in_sizes, int n_in,
                              void* d_out, int out_size)
{
    const float* x  = (const float*)d_in[0];
    const float* Wq = (const float*)d_in[1];
    const float* Wk = (const float*)d_in[2];
    const float* Wv = (const float*)d_in[3];
    const float* Wo = (const float*)d_in[4];
    float* out = (float*)d_out;

    float *q, *k, *v, *m;
    cudaGetSymbolAddress((void**)&q, g_q);
    cudaGetSymbolAddress((void**)&k, g_k);
    cudaGetSymbolAddress((void**)&v, g_v);
    cudaGetSymbolAddress((void**)&m, g_m);

    const int M = BSZ*SEQ, N = EMB, K = EMB;
    dim3 ggrid(N/128, M/128);

    cudaFuncSetAttribute(tgemm<0>, cudaFuncAttributeMaxDynamicSharedMemorySize, TG_SMEM);
    cudaFuncSetAttribute(tgemm<1>, cudaFuncAttributeMaxDynamicSharedMemorySize, TG_SMEM);
    cudaFuncSetAttribute(attn_tc, cudaFuncAttributeMaxDynamicSharedMemorySize, ATT_SMEM);

    tgemm<1><<<ggrid, 256, TG_SMEM>>>(x, Wq, q, M, N, K);
    tgemm<1><<<ggrid, 256, TG_SMEM>>>(x, Wk, k, M, N, K);
    tgemm<1><<<ggrid, 256, TG_SMEM>>>(x, Wv, v, M, N, K);

    attn_tc<<<dim3(SEQ/128, BH), 256, ATT_SMEM>>>(q, k, v, m);

    tgemm<0><<<ggrid, 256, TG_SMEM>>>(m, Wo, out, M, N, K);
}

// round 11
// speedup vs baseline: 7.0581x; 1.8080x over previous
#include <cuda_runtime.h>
#include <cuda_fp16.h>
#include <cstdint>

#define EMB  1024
#define NH   16
#define HD   64
#define BSZ  4
#define SEQ  2048
#define BH   (BSZ*NH)

// fp32 scratch
__device__ float  g_q[BH*SEQ*HD];
__device__ float  g_k[BH*SEQ*HD];
__device__ float  g_v[BH*SEQ*HD];
// fp16 scratch
__device__ __half g_xh[BSZ*SEQ*EMB];       // x in fp16
__device__ __half g_wqkvh[3*EMB*EMB];      // Wq|Wk|Wv fp16, [3072,1024]
__device__ __half g_woh[EMB*EMB];          // Wo fp16
__device__ __half g_mh[BSZ*SEQ*EMB];       // merged attention output fp16

__device__ __forceinline__ uint32_t h2u(__half2 h) {
    union { __half2 h; uint32_t u; } c; c.h = h; return c.u;
}
__device__ __forceinline__ uint32_t smem_u32(const void* p) {
    uint32_t a;
    asm("{ .reg .u64 t; cvta.to.shared.u64 t, %1; cvt.u32.u64 %0, t; }" : "=r"(a) : "l"(p));
    return a;
}
__device__ __forceinline__ uint64_t gptr(const void* p) {
    uint64_t r; asm("cvta.to.global.u64 %0, %1;" : "=l"(r) : "l"(p)); return r;
}
__device__ __forceinline__ void mma_f16(float* c, const uint32_t* a, uint32_t b0, uint32_t b1) {
    asm volatile(
        "mma.sync.aligned.m16n8k16.row.col.f32.f16.f16.f32 "
        "{%0,%1,%2,%3}, {%4,%5,%6,%7}, {%8,%9}, {%0,%1,%2,%3};"
        : "+f"(c[0]), "+f"(c[1]), "+f"(c[2]), "+f"(c[3])
        : "r"(a[0]), "r"(a[1]), "r"(a[2]), "r"(a[3]), "r"(b0), "r"(b1));
}

// ---------------------------------------------------------------------------
// fp32 -> fp16 bulk convert (vectorized)
// ---------------------------------------------------------------------------
__global__ void f2h_kn(const float4* __restrict__ src, __half2* __restrict__ dst, int n4)
{
    int i = blockIdx.x * blockDim.x + threadIdx.x;
    if (i < n4) {
        float4 v = src[i];
        dst[2*i]   = __floats2half2_rn(v.x, v.y);
        dst[2*i+1] = __floats2half2_rn(v.z, v.w);
    }
}

// ---------------------------------------------------------------------------
// fp16 GEMM, cp.async 4-stage + ldmatrix + m16n8k16.
// C = A[M,K]h @ W[N,K]h^T, fp32 out.
// Block 256 thr = 8 warps (2m x 4n), tile 128x128, K-chunk 64.
// Stage = A 128x128B + B 128x128B = 32KB; 4 stages = 128KB dyn smem.
// MODE 0: C row-major [M,N] (Cq).  MODE 1: head-split, base chosen by n>>10
//         from {Cq,Ck,Cv}.
// ---------------------------------------------------------------------------
#define TGH_SMEM (4 * 32768)

template<int MODE>
__global__ void __launch_bounds__(256) tgemm_h(const __half* __restrict__ A,
                                               const __half* __restrict__ W,
                                               float* __restrict__ Cq,
                                               float* __restrict__ Ck,
                                               float* __restrict__ Cv,
                                               int M, int N, int K)
{
    extern __shared__ __align__(16) char smc[];
    const int tid = threadIdx.x, lane = tid & 31, wid = tid >> 5;
    const int wm = wid & 1, wn = wid >> 1;
    const int bm = blockIdx.y * 128, bn = blockIdx.x * 128;
    const uint32_t sbase = smem_u32(smc);

    const uint64_t gA = gptr(A) + (size_t)bm * K * 2;
    const uint64_t gB = gptr(W) + (size_t)bn * K * 2;

    // cp.async geometry: idx = tid + i*256; r = idx>>3, c8 = idx&7 (16B chunks)
    const int cr  = tid >> 3, cc8 = tid & 7;
    const uint32_t csw = ((uint32_t)(cc8 * 16)) ^ (((uint32_t)cr & 7) << 4);

    float acc[4][4][4];
#pragma unroll
    for (int i = 0; i < 4; i++)
#pragma unroll
        for (int j = 0; j < 4; j++)
#pragma unroll
            for (int r = 0; r < 4; r++) acc[i][j][r] = 0.f;

    const int KIT = K / 64;   // 16

#define TGH_ISSUE(kt, s)                                                          \
    do {                                                                          \
        uint32_t sA = sbase + (s) * 32768;                                        \
        uint64_t goff = ((size_t)(kt) * 64 + cc8 * 8) * 2;                        \
        _Pragma("unroll")                                                         \
        for (int i = 0; i < 4; i++) {                                             \
            int r = cr + i * 32;                                                  \
            uint32_t so = sA + r * 128 + csw;                                     \
            uint64_t ga = gA + (size_t)r * K * 2 + goff;                          \
            uint64_t gb = gB + (size_t)r * K * 2 + goff;                          \
            asm volatile("cp.async.cg.shared.global [%0], [%1], 16;" :: "r"(so), "l"(ga)); \
            asm volatile("cp.async.cg.shared.global [%0], [%1], 16;" :: "r"(so + 16384), "l"(gb)); \
        }                                                                         \
        asm volatile("cp.async.commit_group;");                                   \
    } while (0)

    TGH_ISSUE(0, 0);
    TGH_ISSUE(1, 1);
    TGH_ISSUE(2, 2);

    // ldmatrix address geometry (constant parts)
    const int l8 = lane & 7;
    const int rowA0 = wm * 64 + l8 + 8 * ((lane >> 3) & 1);   // + mt*16
    const int colA0 = 16 * (lane >> 4);                        // + ks*32
    const uint32_t xorA = ((uint32_t)rowA0 & 7) << 4;
    const int rowB0 = wn * 32 + l8 + 8 * (lane >> 4);          // + j2*16
    const int colB0 = 16 * ((lane >> 3) & 1);                  // + ks*32
    const uint32_t xorB = ((uint32_t)rowB0 & 7) << 4;

    for (int it = 0; it < KIT; it++) {
        asm volatile("cp.async.wait_group 2;");
        __syncthreads();

        const uint32_t aT = sbase + (it & 3) * 32768;
        const uint32_t bT = aT + 16384;

#pragma unroll
        for (int ks = 0; ks < 4; ks++) {
            uint32_t af[4][4], bf[4][2];
#pragma unroll
            for (int mt = 0; mt < 4; mt++) {
                uint32_t addr = aT + (rowA0 + mt * 16) * 128 + ((ks * 32 + colA0) ^ xorA);
                asm volatile("ldmatrix.sync.aligned.m8n8.x4.shared.b16 {%0,%1,%2,%3}, [%4];"
                             : "=r"(af[mt][0]), "=r"(af[mt][1]), "=r"(af[mt][2]), "=r"(af[mt][3])
                             : "r"(addr));
            }
#pragma unroll
            for (int j2 = 0; j2 < 2; j2++) {
                uint32_t addr = bT + (rowB0 + j2 * 16) * 128 + ((ks * 32 + colB0) ^ xorB);
                asm volatile("ldmatrix.sync.aligned.m8n8.x4.shared.b16 {%0,%1,%2,%3}, [%4];"
                             : "=r"(bf[j2*2][0]), "=r"(bf[j2*2][1]),
                               "=r"(bf[j2*2+1][0]), "=r"(bf[j2*2+1][1])
                             : "r"(addr));
            }
#pragma unroll
            for (int mt = 0; mt < 4; mt++)
#pragma unroll
                for (int nt = 0; nt < 4; nt++)
                    mma_f16(acc[mt][nt], af[mt], bf[nt][0], bf[nt][1]);
        }

        if (it + 3 < KIT) { TGH_ISSUE(it + 3, (it + 3) & 3); }
        else { asm volatile("cp.async.commit_group;"); }
    }
#undef TGH_ISSUE

    // epilogue
    float* base = Cq;
    if (MODE == 1) {
        const int which = bn >> 10;
        base = (which == 0) ? Cq : (which == 1) ? Ck : Cv;
    }
#pragma unroll
    for (int i = 0; i < 4; i++) {
#pragma unroll
        for (int j = 0; j < 4; j++) {
            const int m0 = bm + wm * 64 + i * 16 + (lane >> 2);
            const int n0 = bn + wn * 32 + j * 8 + (lane & 3) * 2;
            float2 lo = { acc[i][j][0], acc[i][j][1] };
            float2 hi = { acc[i][j][2], acc[i][j][3] };
            if (MODE == 0) {
                *(float2*)(base + (size_t)m0 * N + n0) = lo;
                *(float2*)(base + (size_t)(m0 + 8) * N + n0) = hi;
            } else {
                const int nl = n0 & 1023;
                const int h = nl >> 6, d = nl & 63;
                const int b0 = m0 >> 11, s0 = m0 & (SEQ - 1);
                *(float2*)(base + ((size_t)((b0*NH + h)*SEQ + s0) << 6) + d) = lo;
                const int m1 = m0 + 8;
                const int b1 = m1 >> 11, s1 = m1 & (SEQ - 1);
                *(float2*)(base + ((size_t)((b1*NH + h)*SEQ + s1) << 6) + d) = hi;
            }
        }
    }
}

// ---------------------------------------------------------------------------
// fp16 tensor-core flash attention (round 7/8 kernel; output now fp16)
// ---------------------------------------------------------------------------
#define QLD 68
#define KVH 4352
#define ATT_SMEM (128*QLD*4 + 4*KVH*2)

__device__ __forceinline__ void store_kv(__half* Kd, __half* Vd,
                                         int key, int d0, float4 kv, float4 vv)
{
    const int nt = key >> 3, gk = key & 7, ksK = d0 >> 4;
    const int t0 = (d0 >> 1) & 3, regK = (d0 >> 3) & 1, swK = ksK & 3;
    __half* kb = Kd + (nt*4 + ksK)*136 + gk*16 + regK*2;
    *(__half2*)(kb + ((t0    ) ^ swK)*4) = __floats2half2_rn(kv.x, kv.y);
    *(__half2*)(kb + ((t0 + 1) ^ swK)*4) = __floats2half2_rn(kv.z, kv.w);

    const int ksV = key >> 4, tV = (key >> 1) & 3, regV = (key >> 3) & 1, loV = key & 1;
    const int dt = d0 >> 3, gv0 = d0 & 7;
    const int tV2 = tV ^ (dt & 3);
    __half* vb = Vd + (dt*4 + ksV)*136 + gv0*16 + tV2*4 + regV*2 + loV;
    vb[0]  = __float2half_rn(vv.x);
    vb[16] = __float2half_rn(vv.y);
    vb[32] = __float2half_rn(vv.z);
    vb[48] = __float2half_rn(vv.w);
}

__global__ void __launch_bounds__(256) attn_tc(const float* __restrict__ Qg,
                                               const float* __restrict__ Kg,
                                               const float* __restrict__ Vg,
                                               __half* __restrict__ Out)
{
    extern __shared__ float sm[];
    float* Qs = sm;
    __half* KfB = (__half*)(sm + 128*QLD);
    __half* VfB = KfB + 2*KVH;

    const int qt = (SEQ/128 - 1) - blockIdx.x;
    const int bh = blockIdx.y;
    const int b = bh >> 4, h = bh & 15;
    const int tid = threadIdx.x, w = tid >> 5, lane = tid & 31;
    const int g = lane >> 2, t = lane & 3;

    const float* Qb = Qg + (size_t)(bh*SEQ + qt*128)*HD;
    const float* Kb = Kg + (size_t)bh*SEQ*HD;
    const float* Vb = Vg + (size_t)bh*SEQ*HD;

    int keyv[4], d0v[4];
#pragma unroll
    for (int i = 0; i < 4; i++) {
        int f4 = tid + i*256;
        keyv[i] = f4 >> 4;
        d0v[i]  = (f4 & 15) * 4;
    }

    for (int i = tid; i < 128*16; i += 256) {
        int r = i >> 4, c4 = (i & 15) << 2;
        float4 v = *(const float4*)(Qb + r*HD + c4);
        float* p = Qs + r*QLD + c4;
        p[0]=v.x; p[1]=v.y; p[2]=v.z; p[3]=v.w;
    }
    __syncthreads();

    uint32_t qf[4][4];
    {
        const float sc = 0.125f * 1.44269504088896340736f;
        const int r0 = w*16 + g;
#pragma unroll
        for (int ks = 0; ks < 4; ks++) {
            const int c0 = ks*16 + 2*t;
            qf[ks][0] = h2u(__floats2half2_rn(Qs[r0*QLD + c0]*sc,     Qs[r0*QLD + c0+1]*sc));
            qf[ks][1] = h2u(__floats2half2_rn(Qs[(r0+8)*QLD + c0]*sc, Qs[(r0+8)*QLD + c0+1]*sc));
            qf[ks][2] = h2u(__floats2half2_rn(Qs[r0*QLD + c0+8]*sc,   Qs[r0*QLD + c0+9]*sc));
            qf[ks][3] = h2u(__floats2half2_rn(Qs[(r0+8)*QLD + c0+8]*sc, Qs[(r0+8)*QLD + c0+9]*sc));
        }
    }

    float mrow[2] = { -1e30f, -1e30f };
    float lrow[2] = { 0.f, 0.f };
    float oacc[8][4];
#pragma unroll
    for (int i = 0; i < 8; i++)
#pragma unroll
        for (int r = 0; r < 4; r++) oacc[i][r] = 0.f;

    const int nkt = 2*qt + 2;

#pragma unroll
    for (int i = 0; i < 4; i++) {
        float4 kv = *(const float4*)(Kb + keyv[i]*HD + d0v[i]);
        float4 vv = *(const float4*)(Vb + keyv[i]*HD + d0v[i]);
        store_kv(KfB, VfB, keyv[i], d0v[i], kv, vv);
    }
    __syncthreads();

    for (int kt = 0; kt < nkt; kt++) {
        const bool pref = (kt + 1 < nkt);
        float4 kpf[4], vpf[4];
        if (pref) {
            const float* Kt = Kb + (size_t)(kt+1)*64*HD;
            const float* Vt = Vb + (size_t)(kt+1)*64*HD;
#pragma unroll
            for (int i = 0; i < 4; i++) {
                kpf[i] = *(const float4*)(Kt + keyv[i]*HD + d0v[i]);
                vpf[i] = *(const float4*)(Vt + keyv[i]*HD + d0v[i]);
            }
        }

        const __half* Kf = KfB + (kt & 1) * KVH;
        const __half* Vf = VfB + (kt & 1) * KVH;

        float sacc[8][4];
#pragma unroll
        for (int nt = 0; nt < 8; nt++)
#pragma unroll
            for (int r = 0; r < 4; r++) sacc[nt][r] = 0.f;

#pragma unroll
        for (int ks = 0; ks < 4; ks++) {
            const int tp = (t ^ (ks & 3)) * 4;
#pragma unroll
            for (int nt = 0; nt < 8; nt++) {
                uint2 bfr = *(const uint2*)(Kf + (nt*4 + ks)*136 + g*16 + tp);
                mma_f16(sacc[nt], qf[ks], bfr.x, bfr.y);
            }
        }

        if (kt >= 2*qt) {
            const int row0 = qt*128 + w*16 + g;
            const int colb = kt*64 + 2*t;
#pragma unroll
            for (int nt = 0; nt < 8; nt++) {
                int c = colb + nt*8;
                if (c     > row0)     sacc[nt][0] = -1e30f;
                if (c + 1 > row0)     sacc[nt][1] = -1e30f;
                if (c     > row0 + 8) sacc[nt][2] = -1e30f;
                if (c + 1 > row0 + 8) sacc[nt][3] = -1e30f;
            }
        }

#pragma unroll
        for (int hh = 0; hh < 2; hh++) {
            const int i0 = hh*2;
            float mx = -1e30f;
#pragma unroll
            for (int nt = 0; nt < 8; nt++)
                mx = fmaxf(mx, fmaxf(sacc[nt][i0], sacc[nt][i0+1]));
            mx = fmaxf(mx, __shfl_xor_sync(0xffffffffu, mx, 1));
            mx = fmaxf(mx, __shfl_xor_sync(0xffffffffu, mx, 2));
            float mnew = fmaxf(mrow[hh], mx);
            float corr = exp2f(mrow[hh] - mnew);
            mrow[hh] = mnew;
            float sum = 0.f;
#pragma unroll
            for (int nt = 0; nt < 8; nt++) {
                sacc[nt][i0]   = exp2f(sacc[nt][i0]   - mnew);
                sacc[nt][i0+1] = exp2f(sacc[nt][i0+1] - mnew);
                sum += sacc[nt][i0] + sacc[nt][i0+1];
            }
            sum += __shfl_xor_sync(0xffffffffu, sum, 1);
            sum += __shfl_xor_sync(0xffffffffu, sum, 2);
            lrow[hh] = lrow[hh]*corr + sum;
#pragma unroll
            for (int dt = 0; dt < 8; dt++) {
                oacc[dt][i0]   *= corr;
                oacc[dt][i0+1] *= corr;
            }
        }

#pragma unroll
        for (int ks = 0; ks < 4; ks++) {
            uint32_t pf[4];
            pf[0] = h2u(__floats2half2_rn(sacc[2*ks][0],   sacc[2*ks][1]));
            pf[1] = h2u(__floats2half2_rn(sacc[2*ks][2],   sacc[2*ks][3]));
            pf[2] = h2u(__floats2half2_rn(sacc[2*ks+1][0], sacc[2*ks+1][1]));
            pf[3] = h2u(__floats2half2_rn(sacc[2*ks+1][2], sacc[2*ks+1][3]));
#pragma unroll
            for (int dt = 0; dt < 8; dt++) {
                uint2 bfr = *(const uint2*)(Vf + (dt*4 + ks)*136 + g*16 + (t ^ (dt & 3))*4);
                mma_f16(oacc[dt], pf, bfr.x, bfr.y);
            }
        }

        if (pref) {
            __half* Kd = KfB + ((kt+1) & 1) * KVH;
            __half* Vd = VfB + ((kt+1) & 1) * KVH;
#pragma unroll
            for (int i = 0; i < 4; i++)
                store_kv(Kd, Vd, keyv[i], d0v[i], kpf[i], vpf[i]);
        }
        __syncthreads();
    }

    const float inv0 = 1.0f / lrow[0];
    const float inv1 = 1.0f / lrow[1];
    const int row0 = qt*128 + w*16 + g;
#pragma unroll
    for (int dt = 0; dt < 8; dt++) {
        const int col = h*64 + dt*8 + 2*t;
        *(__half2*)(Out + (size_t)(b*SEQ + row0)*EMB + col) =
            __floats2half2_rn(oacc[dt][0]*inv0, oacc[dt][1]*inv0);
        *(__half2*)(Out + (size_t)(b*SEQ + row0 + 8)*EMB + col) =
            __floats2half2_rn(oacc[dt][2]*inv1, oacc[dt][3]*inv1);
    }
}

extern "C" void kernel_launch(void* const* d_in, const int* in_sizes, int n_in,
                              void* d_out, int out_size)
{
    const float* x  = (const float*)d_in[0];
    const float* Wq = (const float*)d_in[1];
    const float* Wk = (const float*)d_in[2];
    const float* Wv = (const float*)d_in[3];
    const float* Wo = (const float*)d_in[4];
    float* out = (float*)d_out;

    float *q, *k, *v;
    __half *xh, *wqkvh, *woh, *mh;
    cudaGetSymbolAddress((void**)&q, g_q);
    cudaGetSymbolAddress((void**)&k, g_k);
    cudaGetSymbolAddress((void**)&v, g_v);
    cudaGetSymbolAddress((void**)&xh, g_xh);
    cudaGetSymbolAddress((void**)&wqkvh, g_wqkvh);
    cudaGetSymbolAddress((void**)&woh, g_woh);
    cudaGetSymbolAddress((void**)&mh, g_mh);

    const int M = BSZ*SEQ, K = EMB;
    const int NX4 = (M*K)/4, NW4 = (EMB*EMB)/4;

    // converts
    f2h_kn<<<(NX4+255)/256, 256>>>((const float4*)x,  (__half2*)xh, NX4);
    f2h_kn<<<(NW4+255)/256, 256>>>((const float4*)Wq, (__half2*)(wqkvh),           NW4);
    f2h_kn<<<(NW4+255)/256, 256>>>((const float4*)Wk, (__half2*)(wqkvh + EMB*EMB), NW4);
    f2h_kn<<<(NW4+255)/256, 256>>>((const float4*)Wv, (__half2*)(wqkvh + 2*EMB*EMB), NW4);
    f2h_kn<<<(NW4+255)/256, 256>>>((const float4*)Wo, (__half2*)woh, NW4);

    cudaFuncSetAttribute(tgemm_h<0>, cudaFuncAttributeMaxDynamicSharedMemorySize, TGH_SMEM);
    cudaFuncSetAttribute(tgemm_h<1>, cudaFuncAttributeMaxDynamicSharedMemorySize, TGH_SMEM);
    cudaFuncSetAttribute(attn_tc, cudaFuncAttributeMaxDynamicSharedMemorySize, ATT_SMEM);

    // fused QKV projection: N = 3072
    tgemm_h<1><<<dim3(3*EMB/128, M/128), 256, TGH_SMEM>>>(xh, wqkvh, q, k, v, M, 3*EMB, K);

    attn_tc<<<dim3(SEQ/128, BH), 256, ATT_SMEM>>>(q, k, v, mh);

    // output projection
    tgemm_h<0><<<dim3(EMB/128, M/128), 256, TGH_SMEM>>>(mh, woh, out, nullptr, nullptr, M, EMB, K);
}

// round 12
// speedup vs baseline: 8.8405x; 1.2525x over previous
#include <cuda_runtime.h>
#include <cuda_fp16.h>
#include <cstdint>

#define EMB  1024
#define NH   16
#define HD   64
#define BSZ  4
#define SEQ  2048
#define BH   (BSZ*NH)

// fp16 scratch
__device__ __half g_qh[BH*SEQ*HD];
__device__ __half g_kh[BH*SEQ*HD];
__device__ __half g_vh[BH*SEQ*HD];
__device__ __half g_xh[BSZ*SEQ*EMB];
__device__ __half g_wqkvh[3*EMB*EMB];
__device__ __half g_woh[EMB*EMB];
__device__ __half g_mh[BSZ*SEQ*EMB];

__device__ __forceinline__ uint32_t h2u(__half2 h) {
    union { __half2 h; uint32_t u; } c; c.h = h; return c.u;
}
__device__ __forceinline__ uint32_t smem_u32(const void* p) {
    uint32_t a;
    asm("{ .reg .u64 t; cvta.to.shared.u64 t, %1; cvt.u32.u64 %0, t; }" : "=r"(a) : "l"(p));
    return a;
}
__device__ __forceinline__ uint64_t gptr(const void* p) {
    uint64_t r; asm("cvta.to.global.u64 %0, %1;" : "=l"(r) : "l"(p)); return r;
}
__device__ __forceinline__ void mma_f16(float* c, const uint32_t* a, uint32_t b0, uint32_t b1) {
    asm volatile(
        "mma.sync.aligned.m16n8k16.row.col.f32.f16.f16.f32 "
        "{%0,%1,%2,%3}, {%4,%5,%6,%7}, {%8,%9}, {%0,%1,%2,%3};"
        : "+f"(c[0]), "+f"(c[1]), "+f"(c[2]), "+f"(c[3])
        : "r"(a[0]), "r"(a[1]), "r"(a[2]), "r"(a[3]), "r"(b0), "r"(b1));
}
__device__ __forceinline__ void ldsm4(uint32_t* r, uint32_t addr) {
    asm volatile("ldmatrix.sync.aligned.m8n8.x4.shared.b16 {%0,%1,%2,%3}, [%4];"
                 : "=r"(r[0]), "=r"(r[1]), "=r"(r[2]), "=r"(r[3]) : "r"(addr));
}
__device__ __forceinline__ void ldsm4t(uint32_t* r, uint32_t addr) {
    asm volatile("ldmatrix.sync.aligned.m8n8.x4.trans.shared.b16 {%0,%1,%2,%3}, [%4];"
                 : "=r"(r[0]), "=r"(r[1]), "=r"(r[2]), "=r"(r[3]) : "r"(addr));
}
__device__ __forceinline__ void cpasync16(uint32_t dst, uint64_t src) {
    asm volatile("cp.async.cg.shared.global [%0], [%1], 16;" :: "r"(dst), "l"(src));
}

// ---------------------------------------------------------------------------
__global__ void f2h_kn(const float4* __restrict__ src, __half2* __restrict__ dst, int n4)
{
    int i = blockIdx.x * blockDim.x + threadIdx.x;
    if (i < n4) {
        float4 v = src[i];
        dst[2*i]   = __floats2half2_rn(v.x, v.y);
        dst[2*i+1] = __floats2half2_rn(v.z, v.w);
    }
}

// ---------------------------------------------------------------------------
// fp16 GEMM, cp.async 4-stage + ldmatrix + m16n8k16.
// MODE 0: fp32 out row-major.  MODE 1: fp16 out head-split into Qh/Kh/Vh.
// ---------------------------------------------------------------------------
#define TGH_SMEM (4 * 32768)

template<int MODE>
__global__ void __launch_bounds__(256) tgemm_h(const __half* __restrict__ A,
                                               const __half* __restrict__ W,
                                               float* __restrict__ Cf,
                                               __half* __restrict__ Qh,
                                               __half* __restrict__ Kh,
                                               __half* __restrict__ Vh,
                                               int M, int N, int K)
{
    extern __shared__ __align__(16) char smc[];
    const int tid = threadIdx.x, lane = tid & 31, wid = tid >> 5;
    const int wm = wid & 1, wn = wid >> 1;
    const int bm = blockIdx.y * 128, bn = blockIdx.x * 128;
    const uint32_t sbase = smem_u32(smc);

    const uint64_t gA = gptr(A) + (size_t)bm * K * 2;
    const uint64_t gB = gptr(W) + (size_t)bn * K * 2;

    const int cr  = tid >> 3, cc8 = tid & 7;
    const uint32_t csw = ((uint32_t)(cc8 * 16)) ^ (((uint32_t)cr & 7) << 4);

    float acc[4][4][4];
#pragma unroll
    for (int i = 0; i < 4; i++)
#pragma unroll
        for (int j = 0; j < 4; j++)
#pragma unroll
            for (int r = 0; r < 4; r++) acc[i][j][r] = 0.f;

    const int KIT = K / 64;

#define TGH_ISSUE(kt, s)                                                          \
    do {                                                                          \
        uint32_t sA = sbase + (s) * 32768;                                        \
        uint64_t goff = ((size_t)(kt) * 64 + cc8 * 8) * 2;                        \
        _Pragma("unroll")                                                         \
        for (int i = 0; i < 4; i++) {                                             \
            int r = cr + i * 32;                                                  \
            uint32_t so = sA + r * 128 + csw;                                     \
            cpasync16(so,         gA + (size_t)r * K * 2 + goff);                 \
            cpasync16(so + 16384, gB + (size_t)r * K * 2 + goff);                 \
        }                                                                         \
        asm volatile("cp.async.commit_group;");                                   \
    } while (0)

    TGH_ISSUE(0, 0);
    TGH_ISSUE(1, 1);
    TGH_ISSUE(2, 2);

    const int l8 = lane & 7;
    const int rowA0 = wm * 64 + l8 + 8 * ((lane >> 3) & 1);
    const int colA0 = 16 * (lane >> 4);
    const uint32_t xorA = ((uint32_t)rowA0 & 7) << 4;
    const int rowB0 = wn * 32 + l8 + 8 * (lane >> 4);
    const int colB0 = 16 * ((lane >> 3) & 1);
    const uint32_t xorB = ((uint32_t)rowB0 & 7) << 4;

    for (int it = 0; it < KIT; it++) {
        asm volatile("cp.async.wait_group 2;");
        __syncthreads();

        const uint32_t aT = sbase + (it & 3) * 32768;
        const uint32_t bT = aT + 16384;

#pragma unroll
        for (int ks = 0; ks < 4; ks++) {
            uint32_t af[4][4], bf[4][2];
#pragma unroll
            for (int mt = 0; mt < 4; mt++)
                ldsm4(af[mt], aT + (rowA0 + mt * 16) * 128 + ((ks * 32 + colA0) ^ xorA));
#pragma unroll
            for (int j2 = 0; j2 < 2; j2++) {
                uint32_t r[4];
                ldsm4(r, bT + (rowB0 + j2 * 16) * 128 + ((ks * 32 + colB0) ^ xorB));
                bf[j2*2][0] = r[0]; bf[j2*2][1] = r[1];
                bf[j2*2+1][0] = r[2]; bf[j2*2+1][1] = r[3];
            }
#pragma unroll
            for (int mt = 0; mt < 4; mt++)
#pragma unroll
                for (int nt = 0; nt < 4; nt++)
                    mma_f16(acc[mt][nt], af[mt], bf[nt][0], bf[nt][1]);
        }

        if (it + 3 < KIT) { TGH_ISSUE(it + 3, (it + 3) & 3); }
        else { asm volatile("cp.async.commit_group;"); }
    }
#undef TGH_ISSUE

#pragma unroll
    for (int i = 0; i < 4; i++) {
#pragma unroll
        for (int j = 0; j < 4; j++) {
            const int m0 = bm + wm * 64 + i * 16 + (lane >> 2);
            const int n0 = bn + wn * 32 + j * 8 + (lane & 3) * 2;
            if (MODE == 0) {
                float2 lo = { acc[i][j][0], acc[i][j][1] };
                float2 hi = { acc[i][j][2], acc[i][j][3] };
                *(float2*)(Cf + (size_t)m0 * N + n0) = lo;
                *(float2*)(Cf + (size_t)(m0 + 8) * N + n0) = hi;
            } else {
                const int which = n0 >> 10;
                __half* base = (which == 0) ? Qh : (which == 1) ? Kh : Vh;
                const int nl = n0 & 1023;
                const int h = nl >> 6, d = nl & 63;
                const int b0 = m0 >> 11, s0 = m0 & (SEQ - 1);
                *(__half2*)(base + ((size_t)((b0*NH + h)*SEQ + s0) << 6) + d) =
                    __floats2half2_rn(acc[i][j][0], acc[i][j][1]);
                const int m1 = m0 + 8;
                const int b1 = m1 >> 11, s1 = m1 & (SEQ - 1);
                *(__half2*)(base + ((size_t)((b1*NH + h)*SEQ + s1) << 6) + d) =
                    __floats2half2_rn(acc[i][j][2], acc[i][j][3]);
            }
        }
    }
}

// ---------------------------------------------------------------------------
// fp16 flash attention: cp.async 3-stage K/V + ldmatrix(.trans) + m16n8k16.
// Q/K/V fp16 head-split. Block = 128 q-rows x 1 head, 8 warps. BK=64.
// SMEM: 3 stages x (K 8KB + V 8KB) + Q 16KB = 64KB.
// ---------------------------------------------------------------------------
#define NST   3
#define KVST  (64*128)
#define ATT_SMEM (NST*2*KVST + 128*128)

__global__ void __launch_bounds__(256) attn_tc(const __half* __restrict__ Qg,
                                               const __half* __restrict__ Kg,
                                               const __half* __restrict__ Vg,
                                               __half* __restrict__ Out)
{
    extern __shared__ __align__(16) char smc[];
    const uint32_t sbase = smem_u32(smc);
    const uint32_t qsm   = sbase + NST*2*KVST;

    const int qt = (SEQ/128 - 1) - blockIdx.x;
    const int bh = blockIdx.y;
    const int b = bh >> 4, h = bh & 15;
    const int tid = threadIdx.x, w = tid >> 5, lane = tid & 31;
    const int g = lane >> 2, t = lane & 3;
    const int l8 = lane & 7;

    const uint64_t gQ = gptr(Qg) + (size_t)(bh*SEQ + qt*128)*HD*2;
    const uint64_t gK = gptr(Kg) + (size_t)bh*SEQ*HD*2;
    const uint64_t gV = gptr(Vg) + (size_t)bh*SEQ*HD*2;

    const int cr = tid >> 3, cc = tid & 7;
    const int nkt = 2*qt + 2;

    // ---- issue Q (group), then KV tiles 0,1 ----
#pragma unroll
    for (int i = 0; i < 4; i++) {
        int r = cr + i*32;
        cpasync16(qsm + r*128 + ((cc ^ (r & 7)) << 4), gQ + (size_t)r*128 + cc*16);
    }
    asm volatile("cp.async.commit_group;");

#define KV_ISSUE(kt_)                                                             \
    do {                                                                          \
        if ((kt_) < nkt) {                                                        \
            uint32_t ks_ = sbase + ((kt_) % NST) * 2 * KVST;                      \
            size_t go = (size_t)(kt_) * 64;                                       \
            _Pragma("unroll")                                                     \
            for (int i = 0; i < 2; i++) {                                         \
                int r = cr + i*32;                                                \
                uint32_t sw = ((cc ^ (r & 7)) << 4);                              \
                cpasync16(ks_ + r*128 + sw,        gK + (go + r)*128 + cc*16);    \
                cpasync16(ks_ + KVST + r*128 + sw, gV + (go + r)*128 + cc*16);    \
            }                                                                     \
        }                                                                         \
        asm volatile("cp.async.commit_group;");                                   \
    } while (0)

    KV_ISSUE(0);
    KV_ISSUE(1);

    // ---- wait for Q, build Q fragments (raw fp16) ----
    asm volatile("cp.async.wait_group 2;");
    __syncthreads();

    uint32_t qf[4][4];
    {
        const int r = w*16 + l8 + 8*((lane >> 3) & 1);
        const uint32_t rb = qsm + r*128;
        const uint32_t xr = ((uint32_t)r & 7);
#pragma unroll
        for (int ks = 0; ks < 4; ks++)
            ldsm4(qf[ks], rb + (((uint32_t)(2*ks + (lane >> 4)) ^ xr) << 4));
    }

    float mrow[2] = { -1e30f, -1e30f };
    float lrow[2] = { 0.f, 0.f };
    float oacc[8][4];
#pragma unroll
    for (int i = 0; i < 8; i++)
#pragma unroll
        for (int r = 0; r < 4; r++) oacc[i][r] = 0.f;

    // ldmatrix row geometry
    const int rK = l8 + ((lane >> 4) << 3);          // + ntp*16
    const int rV = l8 + (((lane >> 3) & 1) << 3);    // + ksV*16

    for (int kt = 0; kt < nkt; kt++) {
        asm volatile("cp.async.wait_group 1;");
        __syncthreads();
        KV_ISSUE(kt + 2);

        const uint32_t Kst = sbase + (kt % NST) * 2 * KVST;
        const uint32_t Vst = Kst + KVST;

        // ---- S = Q @ K^T ----
        float sacc[8][4];
#pragma unroll
        for (int nt = 0; nt < 8; nt++)
#pragma unroll
            for (int r = 0; r < 4; r++) sacc[nt][r] = 0.f;

#pragma unroll
        for (int ks = 0; ks < 4; ks++) {
            const uint32_t ch = 2*ks + ((lane >> 3) & 1);
#pragma unroll
            for (int ntp = 0; ntp < 4; ntp++) {
                const int key = ntp*16 + rK;
                uint32_t r4[4];
                ldsm4(r4, Kst + key*128 + ((ch ^ ((uint32_t)key & 7)) << 4));
                mma_f16(sacc[2*ntp],   qf[ks], r4[0], r4[1]);
                mma_f16(sacc[2*ntp+1], qf[ks], r4[2], r4[3]);
            }
        }

        // scale (exact, fp32)
        const float SC = 0.125f * 1.44269504088896340736f;
#pragma unroll
        for (int nt = 0; nt < 8; nt++)
#pragma unroll
            for (int r = 0; r < 4; r++) sacc[nt][r] *= SC;

        // ---- causal mask ----
        if (kt >= 2*qt) {
            const int row0 = qt*128 + w*16 + g;
            const int colb = kt*64 + 2*t;
#pragma unroll
            for (int nt = 0; nt < 8; nt++) {
                int c = colb + nt*8;
                if (c     > row0)     sacc[nt][0] = -1e30f;
                if (c + 1 > row0)     sacc[nt][1] = -1e30f;
                if (c     > row0 + 8) sacc[nt][2] = -1e30f;
                if (c + 1 > row0 + 8) sacc[nt][3] = -1e30f;
            }
        }

        // ---- online softmax (base-2) ----
#pragma unroll
        for (int hh = 0; hh < 2; hh++) {
            const int i0 = hh*2;
            float mx = -1e30f;
#pragma unroll
            for (int nt = 0; nt < 8; nt++)
                mx = fmaxf(mx, fmaxf(sacc[nt][i0], sacc[nt][i0+1]));
            mx = fmaxf(mx, __shfl_xor_sync(0xffffffffu, mx, 1));
            mx = fmaxf(mx, __shfl_xor_sync(0xffffffffu, mx, 2));
            float mnew = fmaxf(mrow[hh], mx);
            float corr = exp2f(mrow[hh] - mnew);
            mrow[hh] = mnew;
            float sum = 0.f;
#pragma unroll
            for (int nt = 0; nt < 8; nt++) {
                sacc[nt][i0]   = exp2f(sacc[nt][i0]   - mnew);
                sacc[nt][i0+1] = exp2f(sacc[nt][i0+1] - mnew);
                sum += sacc[nt][i0] + sacc[nt][i0+1];
            }
            sum += __shfl_xor_sync(0xffffffffu, sum, 1);
            sum += __shfl_xor_sync(0xffffffffu, sum, 2);
            lrow[hh] = lrow[hh]*corr + sum;
#pragma unroll
            for (int dt = 0; dt < 8; dt++) {
                oacc[dt][i0]   *= corr;
                oacc[dt][i0+1] *= corr;
            }
        }

        // ---- O += P @ V  (P from registers; V frags via ldmatrix.trans) ----
#pragma unroll
        for (int ksV = 0; ksV < 4; ksV++) {
            uint32_t pf[4];
            pf[0] = h2u(__floats2half2_rn(sacc[2*ksV][0],   sacc[2*ksV][1]));
            pf[1] = h2u(__floats2half2_rn(sacc[2*ksV][2],   sacc[2*ksV][3]));
            pf[2] = h2u(__floats2half2_rn(sacc[2*ksV+1][0], sacc[2*ksV+1][1]));
            pf[3] = h2u(__floats2half2_rn(sacc[2*ksV+1][2], sacc[2*ksV+1][3]));
            const int row = ksV*16 + rV;
            const uint32_t rb = Vst + row*128;
            const uint32_t xr = (uint32_t)row & 7;
#pragma unroll
            for (int dtp = 0; dtp < 4; dtp++) {
                uint32_t r4[4];
                ldsm4t(r4, rb + (((uint32_t)(2*dtp + (lane >> 4)) ^ xr) << 4));
                mma_f16(oacc[2*dtp],   pf, r4[0], r4[1]);
                mma_f16(oacc[2*dtp+1], pf, r4[2], r4[3]);
            }
        }
    }
#undef KV_ISSUE

    // ---- epilogue -> merged fp16 [B,S,E] ----
    const float inv0 = 1.0f / lrow[0];
    const float inv1 = 1.0f / lrow[1];
    const int row0 = qt*128 + w*16 + g;
#pragma unroll
    for (int dt = 0; dt < 8; dt++) {
        const int col = h*64 + dt*8 + 2*t;
        *(__half2*)(Out + (size_t)(b*SEQ + row0)*EMB + col) =
            __floats2half2_rn(oacc[dt][0]*inv0, oacc[dt][1]*inv0);
        *(__half2*)(Out + (size_t)(b*SEQ + row0 + 8)*EMB + col) =
            __floats2half2_rn(oacc[dt][2]*inv1, oacc[dt][3]*inv1);
    }
}

extern "C" void kernel_launch(void* const* d_in, const int* in_sizes, int n_in,
                              void* d_out, int out_size)
{
    const float* x  = (const float*)d_in[0];
    const float* Wq = (const float*)d_in[1];
    const float* Wk = (const float*)d_in[2];
    const float* Wv = (const float*)d_in[3];
    const float* Wo = (const float*)d_in[4];
    float* out = (float*)d_out;

    __half *qh, *kh, *vh, *xh, *wqkvh, *woh, *mh;
    cudaGetSymbolAddress((void**)&qh, g_qh);
    cudaGetSymbolAddress((void**)&kh, g_kh);
    cudaGetSymbolAddress((void**)&vh, g_vh);
    cudaGetSymbolAddress((void**)&xh, g_xh);
    cudaGetSymbolAddress((void**)&wqkvh, g_wqkvh);
    cudaGetSymbolAddress((void**)&woh, g_woh);
    cudaGetSymbolAddress((void**)&mh, g_mh);

    const int M = BSZ*SEQ, K = EMB;
    const int NX4 = (M*K)/4, NW4 = (EMB*EMB)/4;

    f2h_kn<<<(NX4+255)/256, 256>>>((const float4*)x,  (__half2*)xh, NX4);
    f2h_kn<<<(NW4+255)/256, 256>>>((const float4*)Wq, (__half2*)(wqkvh),             NW4);
    f2h_kn<<<(NW4+255)/256, 256>>>((const float4*)Wk, (__half2*)(wqkvh + EMB*EMB),   NW4);
    f2h_kn<<<(NW4+255)/256, 256>>>((const float4*)Wv, (__half2*)(wqkvh + 2*EMB*EMB), NW4);
    f2h_kn<<<(NW4+255)/256, 256>>>((const float4*)Wo, (__half2*)woh, NW4);

    cudaFuncSetAttribute(tgemm_h<0>, cudaFuncAttributeMaxDynamicSharedMemorySize, TGH_SMEM);
    cudaFuncSetAttribute(tgemm_h<1>, cudaFuncAttributeMaxDynamicSharedMemorySize, TGH_SMEM);
    cudaFuncSetAttribute(attn_tc, cudaFuncAttributeMaxDynamicSharedMemorySize, ATT_SMEM);

    // fused QKV projection -> fp16 head-split
    tgemm_h<1><<<dim3(3*EMB/128, M/128), 256, TGH_SMEM>>>(xh, wqkvh, nullptr, qh, kh, vh, M, 3*EMB, K);

    attn_tc<<<dim3(SEQ/128, BH), 256, ATT_SMEM>>>(qh, kh, vh, mh);

    // output projection -> fp32
    tgemm_h<0><<<dim3(EMB/128, M/128), 256, TGH_SMEM>>>(mh, woh, out, nullptr, nullptr, nullptr, M, EMB, K);
}